// round 2
// baseline (speedup 1.0000x reference)
#include <cuda_runtime.h>

#define NNODES 100000
#define FIN 64
#define DIM 128
#define SAMP 16
#define TM 64          // nodes per block
#define NTHREADS 256

// Scratch: intermediate embeddings (module-load allocated, not runtime alloc)
__device__ float g_x0[(size_t)NNODES * DIM];
__device__ float g_x1[(size_t)NNODES * DIM];

// ---------------------------------------------------------------------------
// Kernel 1: x0 = feat @ w_feat^T     [N,64] @ [64,128] -> [N,128]
// ---------------------------------------------------------------------------
__global__ __launch_bounds__(NTHREADS, 2)
void feat_kernel(const float* __restrict__ feat,
                 const float* __restrict__ wf,
                 float* __restrict__ out)
{
    extern __shared__ float sm[];
    float* s_wT = sm;               // [FIN][136]  k-major (transposed), padded stride
    float* s_a  = sm + FIN * 136;   // [TM][FIN]

    const int tid = threadIdx.x;
    const int b0  = blockIdx.x * TM;

    // Load w_feat transposed: s_wT[k*136 + j] = wf[j*FIN + k]
    for (int idx = tid; idx < DIM * FIN; idx += NTHREADS) {
        int j = idx / FIN, k = idx % FIN;
        s_wT[k * 136 + j] = wf[idx];
    }
    // Load feature tile (coalesced)
    for (int idx = tid; idx < TM * FIN; idx += NTHREADS) {
        int m = idx / FIN, c = idx % FIN;
        int node = b0 + m;
        if (node >= NNODES) node = NNODES - 1;
        s_a[m * FIN + c] = feat[node * FIN + c];
    }
    __syncthreads();

    const int m0 = (tid >> 5) * 8;   // warp -> 8 consecutive nodes
    const int j0 = (tid & 31) * 4;   // lane -> 4 consecutive outputs

    float acc[8][4];
    #pragma unroll
    for (int mm = 0; mm < 8; mm++)
        #pragma unroll
        for (int jj = 0; jj < 4; jj++) acc[mm][jj] = 0.0f;

    #pragma unroll 2
    for (int k = 0; k < FIN; k += 4) {
        float4 w4[4];
        #pragma unroll
        for (int kk = 0; kk < 4; kk++)
            w4[kk] = *(const float4*)&s_wT[(k + kk) * 136 + j0];
        #pragma unroll
        for (int mm = 0; mm < 8; mm++) {
            float4 av = *(const float4*)&s_a[(m0 + mm) * FIN + k];
            acc[mm][0] += av.x * w4[0].x; acc[mm][1] += av.x * w4[0].y;
            acc[mm][2] += av.x * w4[0].z; acc[mm][3] += av.x * w4[0].w;
            acc[mm][0] += av.y * w4[1].x; acc[mm][1] += av.y * w4[1].y;
            acc[mm][2] += av.y * w4[1].z; acc[mm][3] += av.y * w4[1].w;
            acc[mm][0] += av.z * w4[2].x; acc[mm][1] += av.z * w4[2].y;
            acc[mm][2] += av.z * w4[2].z; acc[mm][3] += av.z * w4[2].w;
            acc[mm][0] += av.w * w4[3].x; acc[mm][1] += av.w * w4[3].y;
            acc[mm][2] += av.w * w4[3].z; acc[mm][3] += av.w * w4[3].w;
        }
    }

    #pragma unroll
    for (int mm = 0; mm < 8; mm++) {
        int node = b0 + m0 + mm;
        if (node < NNODES) {
            float4 v = make_float4(acc[mm][0], acc[mm][1], acc[mm][2], acc[mm][3]);
            *(float4*)&out[(size_t)node * DIM + j0] = v;
        }
    }
}

// ---------------------------------------------------------------------------
// Kernel 2: one SAGE layer (gather-mean + Linear + ReLU + L2-normalize)
// ---------------------------------------------------------------------------
__global__ __launch_bounds__(NTHREADS, 2)
void sage_layer(const float* __restrict__ x,
                const int*   __restrict__ nb,
                const float* __restrict__ w,
                float*       __restrict__ out)
{
    extern __shared__ float sm[];
    float* s_wT  = sm;                // [DIM][136] k-major transposed
    float* s_agg = sm + DIM * 136;    // [TM][DIM]

    const int tid = threadIdx.x;
    const int b0  = blockIdx.x * TM;

    // Load w transposed: s_wT[k*136 + j] = w[j*DIM + k]
    for (int idx = tid; idx < DIM * DIM; idx += NTHREADS) {
        int j = idx >> 7, k = idx & 127;
        s_wT[k * 136 + j] = w[idx];
    }

    // ---- Gather: 4 threads per node, each covers 32 of 128 dims -----------
    {
        const int m = tid >> 2;       // node within block (0..63)
        const int q = tid & 3;        // quarter of each 64B segment
        int node = b0 + m;
        if (node >= NNODES) node = NNODES - 1;

        float4 acc[8];
        const float4* xr = (const float4*)(x + (size_t)node * DIM);
        #pragma unroll
        for (int r = 0; r < 8; r++) acc[r] = xr[r * 4 + q];   // self row

        int nbr[SAMP];
        #pragma unroll
        for (int s = 0; s < SAMP; s++) nbr[s] = nb[node * SAMP + s];

        #pragma unroll
        for (int s = 0; s < SAMP; s++) {
            const float4* p = (const float4*)(x + (size_t)nbr[s] * DIM);
            #pragma unroll
            for (int r = 0; r < 8; r++) {
                float4 v = p[r * 4 + q];
                acc[r].x += v.x; acc[r].y += v.y;
                acc[r].z += v.z; acc[r].w += v.w;
            }
        }
        const float inv = 1.0f / (float)(SAMP + 1);
        #pragma unroll
        for (int r = 0; r < 8; r++) {
            float4 v = acc[r];
            v.x *= inv; v.y *= inv; v.z *= inv; v.w *= inv;
            *(float4*)&s_agg[m * DIM + r * 16 + q * 4] = v;
        }
    }
    __syncthreads();

    // ---- GEMM: h = agg @ w^T, 8m x 4j register tile -----------------------
    const int m0 = (tid >> 5) * 8;
    const int j0 = (tid & 31) * 4;

    float acc[8][4];
    #pragma unroll
    for (int mm = 0; mm < 8; mm++)
        #pragma unroll
        for (int jj = 0; jj < 4; jj++) acc[mm][jj] = 0.0f;

    #pragma unroll 2
    for (int k = 0; k < DIM; k += 4) {
        float4 w4[4];
        #pragma unroll
        for (int kk = 0; kk < 4; kk++)
            w4[kk] = *(const float4*)&s_wT[(k + kk) * 136 + j0];
        #pragma unroll
        for (int mm = 0; mm < 8; mm++) {
            float4 av = *(const float4*)&s_agg[(m0 + mm) * DIM + k];
            acc[mm][0] += av.x * w4[0].x; acc[mm][1] += av.x * w4[0].y;
            acc[mm][2] += av.x * w4[0].z; acc[mm][3] += av.x * w4[0].w;
            acc[mm][0] += av.y * w4[1].x; acc[mm][1] += av.y * w4[1].y;
            acc[mm][2] += av.y * w4[1].z; acc[mm][3] += av.y * w4[1].w;
            acc[mm][0] += av.z * w4[2].x; acc[mm][1] += av.z * w4[2].y;
            acc[mm][2] += av.z * w4[2].z; acc[mm][3] += av.z * w4[2].w;
            acc[mm][0] += av.w * w4[3].x; acc[mm][1] += av.w * w4[3].y;
            acc[mm][2] += av.w * w4[3].z; acc[mm][3] += av.w * w4[3].w;
        }
    }

    // ---- ReLU + L2 normalize (warp owns all 128 cols of its 8 nodes) ------
    float ss[8];
    #pragma unroll
    for (int mm = 0; mm < 8; mm++) {
        float s = 0.0f;
        #pragma unroll
        for (int jj = 0; jj < 4; jj++) {
            float v = acc[mm][jj];
            v = fmaxf(v, 0.0f);
            acc[mm][jj] = v;
            s += v * v;
        }
        ss[mm] = s;
    }
    #pragma unroll
    for (int o = 16; o > 0; o >>= 1)
        #pragma unroll
        for (int mm = 0; mm < 8; mm++)
            ss[mm] += __shfl_xor_sync(0xffffffffu, ss[mm], o);

    #pragma unroll
    for (int mm = 0; mm < 8; mm++) {
        int node = b0 + m0 + mm;
        if (node < NNODES) {
            float nrm = sqrtf(ss[mm]);
            float inv = 1.0f / fmaxf(nrm, 1e-12f);
            float4 v = make_float4(acc[mm][0] * inv, acc[mm][1] * inv,
                                   acc[mm][2] * inv, acc[mm][3] * inv);
            *(float4*)&out[(size_t)node * DIM + j0] = v;
        }
    }
}

// ---------------------------------------------------------------------------
extern "C" void kernel_launch(void* const* d_in, const int* in_sizes, int n_in,
                              void* d_out, int out_size)
{
    const float* feat = (const float*)d_in[0];   // [N, 64]
    const float* wf   = (const float*)d_in[1];   // [128, 64]
    const float* w1   = (const float*)d_in[2];   // [128, 128]
    const float* w2   = (const float*)d_in[3];   // [128, 128]
    const int*   n1   = (const int*)d_in[4];     // [N, 16]
    const int*   n2   = (const int*)d_in[5];     // [N, 16]
    float* out = (float*)d_out;                  // [N, 128]

    void *px0 = nullptr, *px1 = nullptr;
    cudaGetSymbolAddress(&px0, g_x0);
    cudaGetSymbolAddress(&px1, g_x1);

    const size_t SMEM_FEAT  = (size_t)(FIN * 136 + TM * FIN) * sizeof(float);   // ~51 KB
    const size_t SMEM_LAYER = (size_t)(DIM * 136 + TM * DIM) * sizeof(float);   // ~100 KB

    cudaFuncSetAttribute(feat_kernel, cudaFuncAttributeMaxDynamicSharedMemorySize,
                         (int)SMEM_FEAT);
    cudaFuncSetAttribute(sage_layer, cudaFuncAttributeMaxDynamicSharedMemorySize,
                         (int)SMEM_LAYER);

    const int grid = (NNODES + TM - 1) / TM;   // 1563

    feat_kernel<<<grid, NTHREADS, SMEM_FEAT>>>(feat, wf, (float*)px0);
    sage_layer<<<grid, NTHREADS, SMEM_LAYER>>>((const float*)px0, n1, w1, (float*)px1);
    sage_layer<<<grid, NTHREADS, SMEM_LAYER>>>((const float*)px1, n2, w2, out);
}

// round 3
// speedup vs baseline: 2.2735x; 2.2735x over previous
#include <cuda_runtime.h>
#include <cuda_bf16.h>

#define NNODES 100000
#define DIM 128
#define FIN 64
#define SAMP 16

// Scratch (module-load allocated; no runtime alloc)
__device__ float g_z [(size_t)NNODES * DIM];
__device__ float g_x1[(size_t)NNODES * DIM];
__device__ float g_wc[DIM * FIN];

// ---------------------------------------------------------------------------
// wc = w1 @ wf   [128,128]@[128,64] -> [128,64]
// ---------------------------------------------------------------------------
__global__ void wc_kernel(const float* __restrict__ w1,
                          const float* __restrict__ wf,
                          float* __restrict__ wc)
{
    int idx = blockIdx.x * 256 + threadIdx.x;      // 8192 outputs
    if (idx >= DIM * FIN) return;
    int i = idx >> 6, j = idx & 63;
    float s = 0.0f;
    #pragma unroll 8
    for (int t = 0; t < DIM; t++)
        s = fmaf(w1[i * DIM + t], wf[t * FIN + j], s);
    wc[i * FIN + j] = s;
}

// ---------------------------------------------------------------------------
// Dense GEMM: C[nrows,128] = A[nrows,K] @ W[128,K]^T
// bf16 3-term split (hi*hi + hi*lo + lo*hi) on mma.sync.m16n8k16 — ~fp32 acc.
// Block: 256 thr (8 warps), 128 rows/block; warp = 16 rows x 128 cols.
// ---------------------------------------------------------------------------
#define MMA_BF16(D, A0,A1,A2,A3, B0,B1)                                      \
    asm volatile("mma.sync.aligned.m16n8k16.row.col.f32.bf16.bf16.f32 "      \
                 "{%0,%1,%2,%3},{%4,%5,%6,%7},{%8,%9},{%0,%1,%2,%3};"        \
                 : "+f"(D[0]), "+f"(D[1]), "+f"(D[2]), "+f"(D[3])            \
                 : "r"(A0), "r"(A1), "r"(A2), "r"(A3), "r"(B0), "r"(B1))

__device__ __forceinline__ unsigned pack_hi(float2 f, float2& lo)
{
    __nv_bfloat162 h = __float22bfloat162_rn(f);
    float2 hf = __bfloat1622float2(h);
    lo = make_float2(f.x - hf.x, f.y - hf.y);
    return *reinterpret_cast<unsigned*>(&h);
}
__device__ __forceinline__ unsigned pack_lo(float2 l)
{
    __nv_bfloat162 h = __float22bfloat162_rn(l);
    return *reinterpret_cast<unsigned*>(&h);
}

template<int K>
__global__ __launch_bounds__(256, 2)
void gemm_split(const float* __restrict__ A,
                const float* __restrict__ W,
                float* __restrict__ C, int nrows)
{
    constexpr int K2 = K / 2;                      // packed bf16x2 cols
    extern __shared__ unsigned smw[];
    unsigned* Wh = smw;                            // [128*K2]
    unsigned* Wl = smw + DIM * K2;

    const int tid = threadIdx.x;

    // Stage W as packed bf16x2 hi/lo with XOR bank swizzle
    for (int idx = tid; idx < DIM * K2; idx += 256) {
        int n = idx / K2, c2 = idx % K2;
        float2 f = *(const float2*)&W[n * K + 2 * c2];
        float2 l;
        unsigned h = pack_hi(f, l);
        int sc = c2 ^ ((n & 7) << 2);
        Wh[n * K2 + sc] = h;
        Wl[n * K2 + sc] = pack_lo(l);
    }
    __syncthreads();

    const int warp = tid >> 5, lane = tid & 31;
    const int g = lane >> 2, c = lane & 3;

    long mrow = (long)blockIdx.x * 128 + warp * 16 + g;
    long r0 = mrow     < nrows ? mrow     : nrows - 1;
    long r1 = mrow + 8 < nrows ? mrow + 8 : nrows - 1;
    const float* A0 = A + r0 * K;
    const float* A1 = A + r1 * K;

    float d[16][4];
    #pragma unroll
    for (int nt = 0; nt < 16; nt++)
        #pragma unroll
        for (int q = 0; q < 4; q++) d[nt][q] = 0.0f;

    const int gsw = g << 2;

    for (int ks = 0; ks < K / 16; ks++) {
        const int k = ks * 16;
        // A fragments direct from global (L2-resident), hi+lo split
        float2 f0 = *(const float2*)&A0[k + 2 * c];
        float2 f1 = *(const float2*)&A1[k + 2 * c];
        float2 f2 = *(const float2*)&A0[k + 2 * c + 8];
        float2 f3 = *(const float2*)&A1[k + 2 * c + 8];
        float2 l0, l1, l2, l3;
        unsigned ah0 = pack_hi(f0, l0), ah1 = pack_hi(f1, l1);
        unsigned ah2 = pack_hi(f2, l2), ah3 = pack_hi(f3, l3);
        unsigned al0 = pack_lo(l0), al1 = pack_lo(l1);
        unsigned al2 = pack_lo(l2), al3 = pack_lo(l3);

        const int k2 = ks * 8;
        const int col0 = (k2 + c)     ^ gsw;
        const int col1 = (k2 + c + 4) ^ gsw;

        #pragma unroll
        for (int nt = 0; nt < 16; nt++) {
            const int nr = nt * 8 + g;
            unsigned b0h = Wh[nr * K2 + col0], b1h = Wh[nr * K2 + col1];
            unsigned b0l = Wl[nr * K2 + col0], b1l = Wl[nr * K2 + col1];
            MMA_BF16(d[nt], ah0, ah1, ah2, ah3, b0h, b1h);
            MMA_BF16(d[nt], ah0, ah1, ah2, ah3, b0l, b1l);
            MMA_BF16(d[nt], al0, al1, al2, al3, b0h, b1h);
        }
    }

    // Epilogue
    long wr0 = (long)blockIdx.x * 128 + warp * 16 + g;
    long wr1 = wr0 + 8;
    #pragma unroll
    for (int nt = 0; nt < 16; nt++) {
        int col = nt * 8 + 2 * c;
        if (wr0 < nrows)
            *(float2*)&C[wr0 * DIM + col] = make_float2(d[nt][0], d[nt][1]);
        if (wr1 < nrows)
            *(float2*)&C[wr1 * DIM + col] = make_float2(d[nt][2], d[nt][3]);
    }
}

// ---------------------------------------------------------------------------
// gathernorm: out[n] = normalize(relu((z[n] + sum_s z[nb[n,s]]) / 17))
// 4 threads/node, 64 nodes/block. Pure memory kernel (L2-bound gather).
// ---------------------------------------------------------------------------
__global__ __launch_bounds__(256)
void gathernorm(const float* __restrict__ z,
                const int*   __restrict__ nb,
                float*       __restrict__ out)
{
    const int tid = threadIdx.x;
    const int m = tid >> 2;          // node in block
    const int q = tid & 3;           // quarter
    int node = blockIdx.x * 64 + m;
    const bool valid = node < NNODES;
    if (!valid) node = NNODES - 1;

    float4 acc[8];
    const float4* zr = (const float4*)(z + (size_t)node * DIM);
    #pragma unroll
    for (int r = 0; r < 8; r++) acc[r] = zr[r * 4 + q];     // self

    int nbr[SAMP];
    #pragma unroll
    for (int s = 0; s < SAMP; s++) nbr[s] = nb[node * SAMP + s];

    #pragma unroll
    for (int s = 0; s < SAMP; s++) {
        const float4* p = (const float4*)(z + (size_t)nbr[s] * DIM);
        #pragma unroll
        for (int r = 0; r < 8; r++) {
            float4 v = p[r * 4 + q];
            acc[r].x += v.x; acc[r].y += v.y;
            acc[r].z += v.z; acc[r].w += v.w;
        }
    }

    const float inv17 = 1.0f / (float)(SAMP + 1);
    float ss = 0.0f;
    #pragma unroll
    for (int r = 0; r < 8; r++) {
        float4 v = acc[r];
        v.x = fmaxf(v.x * inv17, 0.0f);
        v.y = fmaxf(v.y * inv17, 0.0f);
        v.z = fmaxf(v.z * inv17, 0.0f);
        v.w = fmaxf(v.w * inv17, 0.0f);
        acc[r] = v;
        ss += v.x * v.x + v.y * v.y + v.z * v.z + v.w * v.w;
    }
    // reduce across the 4 threads of this node (quad-aligned lanes)
    ss += __shfl_xor_sync(0xffffffffu, ss, 1);
    ss += __shfl_xor_sync(0xffffffffu, ss, 2);

    const float inv = 1.0f / fmaxf(sqrtf(ss), 1e-12f);
    if (valid) {
        float4* o = (float4*)(out + (size_t)node * DIM);
        #pragma unroll
        for (int r = 0; r < 8; r++) {
            float4 v = acc[r];
            v.x *= inv; v.y *= inv; v.z *= inv; v.w *= inv;
            o[r * 4 + q] = v;
        }
    }
}

// ---------------------------------------------------------------------------
extern "C" void kernel_launch(void* const* d_in, const int* in_sizes, int n_in,
                              void* d_out, int out_size)
{
    const float* feat = (const float*)d_in[0];   // [N, 64]
    const float* wf   = (const float*)d_in[1];   // [128, 64]
    const float* w1   = (const float*)d_in[2];   // [128, 128]
    const float* w2   = (const float*)d_in[3];   // [128, 128]
    const int*   n1   = (const int*)d_in[4];     // [N, 16]
    const int*   n2   = (const int*)d_in[5];     // [N, 16]
    float* out = (float*)d_out;                  // [N, 128]

    void *pz = nullptr, *px1 = nullptr, *pwc = nullptr;
    cudaGetSymbolAddress(&pz, g_z);
    cudaGetSymbolAddress(&px1, g_x1);
    cudaGetSymbolAddress(&pwc, g_wc);
    float* z  = (float*)pz;
    float* x1 = (float*)px1;
    float* wc = (float*)pwc;

    const size_t SM64  = (size_t)2 * DIM * (FIN / 2) * 4;   // 32 KB
    const size_t SM128 = (size_t)2 * DIM * (DIM / 2) * 4;   // 64 KB
    cudaFuncSetAttribute(gemm_split<FIN>, cudaFuncAttributeMaxDynamicSharedMemorySize,
                         (int)SM64);
    cudaFuncSetAttribute(gemm_split<DIM>, cudaFuncAttributeMaxDynamicSharedMemorySize,
                         (int)SM128);

    const int gemm_grid = (NNODES + 127) / 128;   // 782
    const int gn_grid   = (NNODES + 63) / 64;     // 1563

    // wc = w1 @ wf  (folds layer-1 GEMM into the feature GEMM)
    wc_kernel<<<32, 256>>>(w1, wf, wc);
    // z1 = feat @ wc^T
    gemm_split<FIN><<<gemm_grid, 256, SM64>>>(feat, wc, z, NNODES);
    // x1 = normalize(relu(agg(z1)))
    gathernorm<<<gn_grid, 256>>>(z, n1, x1);
    // z2 = x1 @ w2^T
    gemm_split<DIM><<<gemm_grid, 256, SM128>>>(x1, w2, z, NNODES);
    // out = normalize(relu(agg(z2)))
    gathernorm<<<gn_grid, 256>>>(z, n2, out);
}

// round 4
// speedup vs baseline: 2.5034x; 1.1011x over previous
#include <cuda_runtime.h>
#include <cuda_bf16.h>
#include <cuda_fp16.h>

#define NNODES 100000
#define DIM 128
#define FIN 64
#define SAMP 16

// Scratch (module-load allocated; no runtime alloc)
__device__ __half g_z [(size_t)NNODES * DIM];   // pre-aggregation embeddings (fp16)
__device__ float  g_x1[(size_t)NNODES * DIM];   // layer-1 output (fp32)
__device__ float  g_wc[DIM * FIN];              // folded w1 @ wf

// ---------------------------------------------------------------------------
// wc = w1 @ wf   [128,128]@[128,64] -> [128,64]
// ---------------------------------------------------------------------------
__global__ void wc_kernel(const float* __restrict__ w1,
                          const float* __restrict__ wf,
                          float* __restrict__ wc)
{
    int idx = blockIdx.x * 256 + threadIdx.x;      // 8192 outputs
    if (idx >= DIM * FIN) return;
    int i = idx >> 6, j = idx & 63;
    float s = 0.0f;
    #pragma unroll 8
    for (int t = 0; t < DIM; t++)
        s = fmaf(w1[i * DIM + t], wf[t * FIN + j], s);
    wc[i * FIN + j] = s;
}

// ---------------------------------------------------------------------------
// Dense GEMM: C[nrows,128](fp16) = A[nrows,K](fp32) @ W[128,K]^T(fp32)
// bf16 3-term split (hi*hi + hi*lo + lo*hi) on mma.sync.m16n8k16.
// Block: 512 thr (16 warps) = 8 row-slabs x 2 n-halves; 128 rows/block.
// Warp tile: m16 x n64 (nt=8, 32 acc regs). W in smem as uint2{hi,lo}, LDS.64.
// ---------------------------------------------------------------------------
#define MMA_BF16(D, A0,A1,A2,A3, B0,B1)                                      \
    asm volatile("mma.sync.aligned.m16n8k16.row.col.f32.bf16.bf16.f32 "      \
                 "{%0,%1,%2,%3},{%4,%5,%6,%7},{%8,%9},{%0,%1,%2,%3};"        \
                 : "+f"(D[0]), "+f"(D[1]), "+f"(D[2]), "+f"(D[3])            \
                 : "r"(A0), "r"(A1), "r"(A2), "r"(A3), "r"(B0), "r"(B1))

__device__ __forceinline__ unsigned pack_hi(float2 f, float2& lo)
{
    __nv_bfloat162 h = __float22bfloat162_rn(f);
    float2 hf = __bfloat1622float2(h);
    lo = make_float2(f.x - hf.x, f.y - hf.y);
    return *reinterpret_cast<unsigned*>(&h);
}
__device__ __forceinline__ unsigned pack_lo(float2 l)
{
    __nv_bfloat162 h = __float22bfloat162_rn(l);
    return *reinterpret_cast<unsigned*>(&h);
}

template<int K>
__global__ __launch_bounds__(512, 1)
void gemm_split(const float* __restrict__ A,
                const float* __restrict__ W,
                __half* __restrict__ C, int nrows)
{
    constexpr int K2 = K / 2;                       // packed bf16x2 cols
    extern __shared__ uint2 WB[];                   // [DIM][K2]  {hi, lo}

    const int tid = threadIdx.x;

    // Stage W: packed bf16x2 hi/lo interleaved, XOR bank swizzle
    for (int idx = tid; idx < DIM * K2; idx += 512) {
        int n = idx / K2, c2 = idx % K2;
        float2 f = *(const float2*)&W[n * K + 2 * c2];
        float2 l;
        unsigned h = pack_hi(f, l);
        int sc = c2 ^ ((n & 7) << 2);
        WB[n * K2 + sc] = make_uint2(h, pack_lo(l));
    }
    __syncthreads();

    const int warp  = tid >> 5, lane = tid & 31;
    const int slab  = warp >> 1;            // 0..7   -> 16-row slab
    const int nhalf = warp & 1;             // 0..1   -> n columns [0,64) / [64,128)
    const int noff  = nhalf * 64;
    const int g = lane >> 2, c = lane & 3;

    long mrow = (long)blockIdx.x * 128 + slab * 16 + g;
    long r0 = mrow     < nrows ? mrow     : nrows - 1;
    long r1 = mrow + 8 < nrows ? mrow + 8 : nrows - 1;
    const float* A0 = A + r0 * K;
    const float* A1 = A + r1 * K;

    float d[8][4];
    #pragma unroll
    for (int nt = 0; nt < 8; nt++)
        #pragma unroll
        for (int q = 0; q < 4; q++) d[nt][q] = 0.0f;

    const int gsw = g << 2;

    #pragma unroll 2
    for (int ks = 0; ks < K / 16; ks++) {
        const int k = ks * 16;
        // A fragments direct from global (streamed, L2-resident), hi+lo split
        float2 f0 = *(const float2*)&A0[k + 2 * c];
        float2 f1 = *(const float2*)&A1[k + 2 * c];
        float2 f2 = *(const float2*)&A0[k + 2 * c + 8];
        float2 f3 = *(const float2*)&A1[k + 2 * c + 8];
        float2 l0, l1, l2, l3;
        unsigned ah0 = pack_hi(f0, l0), ah1 = pack_hi(f1, l1);
        unsigned ah2 = pack_hi(f2, l2), ah3 = pack_hi(f3, l3);
        unsigned al0 = pack_lo(l0), al1 = pack_lo(l1);
        unsigned al2 = pack_lo(l2), al3 = pack_lo(l3);

        const int k2 = ks * 8;
        const int col0 = (k2 + c)     ^ gsw;
        const int col1 = (k2 + c + 4) ^ gsw;

        #pragma unroll
        for (int nt = 0; nt < 8; nt++) {
            const uint2* Wrow = WB + (size_t)(noff + nt * 8 + g) * K2;
            uint2 b0 = Wrow[col0];
            uint2 b1 = Wrow[col1];
            MMA_BF16(d[nt], ah0, ah1, ah2, ah3, b0.x, b1.x);  // hi*hi
            MMA_BF16(d[nt], ah0, ah1, ah2, ah3, b0.y, b1.y);  // hi*lo
            MMA_BF16(d[nt], al0, al1, al2, al3, b0.x, b1.x);  // lo*hi
        }
    }

    // Epilogue: fp16 output
    long wr0 = (long)blockIdx.x * 128 + slab * 16 + g;
    long wr1 = wr0 + 8;
    #pragma unroll
    for (int nt = 0; nt < 8; nt++) {
        int col = noff + nt * 8 + 2 * c;
        if (wr0 < nrows) {
            __half2 h = __float22half2_rn(make_float2(d[nt][0], d[nt][1]));
            *(__half2*)&C[wr0 * DIM + col] = h;
        }
        if (wr1 < nrows) {
            __half2 h = __float22half2_rn(make_float2(d[nt][2], d[nt][3]));
            *(__half2*)&C[wr1 * DIM + col] = h;
        }
    }
}

// ---------------------------------------------------------------------------
// gathernorm: out[n] = normalize(relu((z[n] + sum_s z[nb[n,s]]) / 17))
// z is fp16 (256B/row). 4 threads/node, 64 nodes/block. L2-bound gather.
// ---------------------------------------------------------------------------
__global__ __launch_bounds__(256)
void gathernorm(const __half* __restrict__ z,
                const int*    __restrict__ nb,
                float*        __restrict__ out)
{
    const int tid = threadIdx.x;
    const int m = tid >> 2;          // node in block
    const int q = tid & 3;           // quarter
    int node = blockIdx.x * 64 + m;
    const bool valid = node < NNODES;
    if (!valid) node = NNODES - 1;

    // acc[r*4+j] covers dims of 16B chunk (r*4+q), half2 j within chunk
    float2 acc[16];
    {
        const uint4* zr = (const uint4*)(z + (size_t)node * DIM);
        #pragma unroll
        for (int r = 0; r < 4; r++) {
            uint4 u = zr[r * 4 + q];
            const __half2* h = (const __half2*)&u;
            #pragma unroll
            for (int j = 0; j < 4; j++) acc[r * 4 + j] = __half22float2(h[j]);
        }
    }

    int nbr[SAMP];
    #pragma unroll
    for (int s = 0; s < SAMP; s++) nbr[s] = nb[node * SAMP + s];

    #pragma unroll
    for (int s = 0; s < SAMP; s++) {
        const uint4* p = (const uint4*)(z + (size_t)nbr[s] * DIM);
        #pragma unroll
        for (int r = 0; r < 4; r++) {
            uint4 u = p[r * 4 + q];
            const __half2* h = (const __half2*)&u;
            #pragma unroll
            for (int j = 0; j < 4; j++) {
                float2 f = __half22float2(h[j]);
                acc[r * 4 + j].x += f.x;
                acc[r * 4 + j].y += f.y;
            }
        }
    }

    const float inv17 = 1.0f / (float)(SAMP + 1);
    float ss = 0.0f;
    #pragma unroll
    for (int i = 0; i < 16; i++) {
        float2 v = acc[i];
        v.x = fmaxf(v.x * inv17, 0.0f);
        v.y = fmaxf(v.y * inv17, 0.0f);
        acc[i] = v;
        ss += v.x * v.x + v.y * v.y;
    }
    // reduce across the 4 threads of this node (quad-aligned lanes)
    ss += __shfl_xor_sync(0xffffffffu, ss, 1);
    ss += __shfl_xor_sync(0xffffffffu, ss, 2);

    const float inv = 1.0f / fmaxf(sqrtf(ss), 1e-12f);
    if (valid) {
        float4* o = (float4*)(out + (size_t)node * DIM);
        #pragma unroll
        for (int r = 0; r < 4; r++) {
            int chunk = r * 4 + q;          // 8-dim chunk
            float4 v0 = make_float4(acc[r*4+0].x * inv, acc[r*4+0].y * inv,
                                    acc[r*4+1].x * inv, acc[r*4+1].y * inv);
            float4 v1 = make_float4(acc[r*4+2].x * inv, acc[r*4+2].y * inv,
                                    acc[r*4+3].x * inv, acc[r*4+3].y * inv);
            o[chunk * 2 + 0] = v0;
            o[chunk * 2 + 1] = v1;
        }
    }
}

// ---------------------------------------------------------------------------
extern "C" void kernel_launch(void* const* d_in, const int* in_sizes, int n_in,
                              void* d_out, int out_size)
{
    const float* feat = (const float*)d_in[0];   // [N, 64]
    const float* wf   = (const float*)d_in[1];   // [128, 64]
    const float* w1   = (const float*)d_in[2];   // [128, 128]
    const float* w2   = (const float*)d_in[3];   // [128, 128]
    const int*   n1   = (const int*)d_in[4];     // [N, 16]
    const int*   n2   = (const int*)d_in[5];     // [N, 16]
    float* out = (float*)d_out;                  // [N, 128]

    void *pz = nullptr, *px1 = nullptr, *pwc = nullptr;
    cudaGetSymbolAddress(&pz, g_z);
    cudaGetSymbolAddress(&px1, g_x1);
    cudaGetSymbolAddress(&pwc, g_wc);
    __half* z  = (__half*)pz;
    float*  x1 = (float*)px1;
    float*  wc = (float*)pwc;

    const size_t SM64  = (size_t)DIM * (FIN / 2) * sizeof(uint2);   // 32 KB
    const size_t SM128 = (size_t)DIM * (DIM / 2) * sizeof(uint2);   // 64 KB
    cudaFuncSetAttribute(gemm_split<FIN>, cudaFuncAttributeMaxDynamicSharedMemorySize,
                         (int)SM64);
    cudaFuncSetAttribute(gemm_split<DIM>, cudaFuncAttributeMaxDynamicSharedMemorySize,
                         (int)SM128);

    const int gemm_grid = (NNODES + 127) / 128;   // 782
    const int gn_grid   = (NNODES + 63) / 64;     // 1563

    // wc = w1 @ wf  (folds layer-1 GEMM into the feature GEMM)
    wc_kernel<<<32, 256>>>(w1, wf, wc);
    // z1 = feat @ wc^T   (fp16 out)
    gemm_split<FIN><<<gemm_grid, 512, SM64>>>(feat, wc, z, NNODES);
    // x1 = normalize(relu(agg(z1)))
    gathernorm<<<gn_grid, 256>>>(z, n1, x1);
    // z2 = x1 @ w2^T     (fp16 out)
    gemm_split<DIM><<<gemm_grid, 512, SM128>>>(x1, w2, z, NNODES);
    // out = normalize(relu(agg(z2)))
    gathernorm<<<gn_grid, 256>>>(z, n2, out);
}

// round 5
// speedup vs baseline: 2.8055x; 1.1207x over previous
#include <cuda_runtime.h>
#include <cuda_bf16.h>
#include <cuda_fp16.h>

#define NNODES 100000
#define DIM 128
#define FIN 64
#define SAMP 16

// Scratch (module-load allocated; no runtime alloc)
__device__ __half g_z [(size_t)NNODES * DIM];   // pre-aggregation embeddings (fp16)
__device__ float  g_x1[(size_t)NNODES * DIM];   // layer-1 output (fp32)
__device__ float  g_wc[DIM * FIN];              // folded w1 @ wf

// ---------------------------------------------------------------------------
// wc = w1 @ wf   [128,128]@[128,64] -> [128,64]
// ---------------------------------------------------------------------------
__global__ void wc_kernel(const float* __restrict__ w1,
                          const float* __restrict__ wf,
                          float* __restrict__ wc)
{
    int idx = blockIdx.x * 256 + threadIdx.x;      // 8192 outputs
    if (idx >= DIM * FIN) return;
    int i = idx >> 6, j = idx & 63;
    float s = 0.0f;
    #pragma unroll 8
    for (int t = 0; t < DIM; t++)
        s = fmaf(w1[i * DIM + t], wf[t * FIN + j], s);
    wc[i * FIN + j] = s;
}

// ---------------------------------------------------------------------------
// Dense GEMM: C[nrows,128](fp16) = A[nrows,K](fp32) @ W[128,K]^T(fp32)
// bf16 3-term split (hi*hi + hi*lo + lo*hi) on mma.sync.m16n8k16.
// Block: 256 thr (8 warps); warp = 16 rows x all 128 cols (nt=16).
// 2 CTAs/SM for latency overlap. W staged as interleaved uint2{hi,lo}, LDS.64.
// ---------------------------------------------------------------------------
#define MMA_BF16(D, A0,A1,A2,A3, B0,B1)                                      \
    asm volatile("mma.sync.aligned.m16n8k16.row.col.f32.bf16.bf16.f32 "      \
                 "{%0,%1,%2,%3},{%4,%5,%6,%7},{%8,%9},{%0,%1,%2,%3};"        \
                 : "+f"(D[0]), "+f"(D[1]), "+f"(D[2]), "+f"(D[3])            \
                 : "r"(A0), "r"(A1), "r"(A2), "r"(A3), "r"(B0), "r"(B1))

__device__ __forceinline__ unsigned pack_hi(float2 f, float2& lo)
{
    __nv_bfloat162 h = __float22bfloat162_rn(f);
    float2 hf = __bfloat1622float2(h);
    lo = make_float2(f.x - hf.x, f.y - hf.y);
    return *reinterpret_cast<unsigned*>(&h);
}
__device__ __forceinline__ unsigned pack_lo(float2 l)
{
    __nv_bfloat162 h = __float22bfloat162_rn(l);
    return *reinterpret_cast<unsigned*>(&h);
}

template<int K>
__global__ __launch_bounds__(256, 2)
void gemm_split(const float* __restrict__ A,
                const float* __restrict__ W,
                __half* __restrict__ C, int nrows)
{
    constexpr int K2 = K / 2;                       // packed bf16x2 cols
    extern __shared__ uint2 WB[];                   // [DIM][K2]  {hi, lo}

    const int tid = threadIdx.x;

    // Stage W: packed bf16x2 hi/lo interleaved, XOR bank swizzle
    for (int idx = tid; idx < DIM * K2; idx += 256) {
        int n = idx / K2, c2 = idx % K2;
        float2 f = *(const float2*)&W[n * K + 2 * c2];
        float2 l;
        unsigned h = pack_hi(f, l);
        int sc = c2 ^ ((n & 7) << 2);
        WB[n * K2 + sc] = make_uint2(h, pack_lo(l));
    }
    __syncthreads();

    const int warp = tid >> 5, lane = tid & 31;
    const int g = lane >> 2, c = lane & 3;

    long mrow = (long)blockIdx.x * 128 + warp * 16 + g;
    long r0 = mrow     < nrows ? mrow     : nrows - 1;
    long r1 = mrow + 8 < nrows ? mrow + 8 : nrows - 1;
    const float* A0 = A + r0 * K;
    const float* A1 = A + r1 * K;

    float d[16][4];
    #pragma unroll
    for (int nt = 0; nt < 16; nt++)
        #pragma unroll
        for (int q = 0; q < 4; q++) d[nt][q] = 0.0f;

    const int gsw = g << 2;

    #pragma unroll 2
    for (int ks = 0; ks < K / 16; ks++) {
        const int k = ks * 16;
        // A fragments direct from global (L2-resident), hi+lo split
        float2 f0 = *(const float2*)&A0[k + 2 * c];
        float2 f1 = *(const float2*)&A1[k + 2 * c];
        float2 f2 = *(const float2*)&A0[k + 2 * c + 8];
        float2 f3 = *(const float2*)&A1[k + 2 * c + 8];
        float2 l0, l1, l2, l3;
        unsigned ah0 = pack_hi(f0, l0), ah1 = pack_hi(f1, l1);
        unsigned ah2 = pack_hi(f2, l2), ah3 = pack_hi(f3, l3);
        unsigned al0 = pack_lo(l0), al1 = pack_lo(l1);
        unsigned al2 = pack_lo(l2), al3 = pack_lo(l3);

        const int k2 = ks * 8;
        const int col0 = (k2 + c)     ^ gsw;
        const int col1 = (k2 + c + 4) ^ gsw;

        #pragma unroll
        for (int nt = 0; nt < 16; nt++) {
            const uint2* Wrow = WB + (size_t)(nt * 8 + g) * K2;
            uint2 b0 = Wrow[col0];
            uint2 b1 = Wrow[col1];
            MMA_BF16(d[nt], ah0, ah1, ah2, ah3, b0.x, b1.x);  // hi*hi
            MMA_BF16(d[nt], ah0, ah1, ah2, ah3, b0.y, b1.y);  // hi*lo
            MMA_BF16(d[nt], al0, al1, al2, al3, b0.x, b1.x);  // lo*hi
        }
    }

    // Epilogue: fp16 output
    long wr0 = (long)blockIdx.x * 128 + warp * 16 + g;
    long wr1 = wr0 + 8;
    #pragma unroll
    for (int nt = 0; nt < 16; nt++) {
        int col = nt * 8 + 2 * c;
        if (wr0 < nrows) {
            __half2 h = __float22half2_rn(make_float2(d[nt][0], d[nt][1]));
            *(__half2*)&C[wr0 * DIM + col] = h;
        }
        if (wr1 < nrows) {
            __half2 h = __float22half2_rn(make_float2(d[nt][2], d[nt][3]));
            *(__half2*)&C[wr1 * DIM + col] = h;
        }
    }
}

// ---------------------------------------------------------------------------
// gathernorm: out[n] = normalize(relu((z[n] + sum_s z[nb[n,s]]) / 17))
// z is fp16 (256B/row). 4 threads/node, 64 nodes/block. L2/LTS-bound gather.
// ---------------------------------------------------------------------------
__global__ __launch_bounds__(256)
void gathernorm(const __half* __restrict__ z,
                const int*    __restrict__ nb,
                float*        __restrict__ out)
{
    const int tid = threadIdx.x;
    const int m = tid >> 2;          // node in block
    const int q = tid & 3;           // quarter
    int node = blockIdx.x * 64 + m;
    const bool valid = node < NNODES;
    if (!valid) node = NNODES - 1;

    // acc[r*4+j] covers dims of 16B chunk (r*4+q), half2 j within chunk
    float2 acc[16];
    {
        const uint4* zr = (const uint4*)(z + (size_t)node * DIM);
        #pragma unroll
        for (int r = 0; r < 4; r++) {
            uint4 u = zr[r * 4 + q];
            const __half2* h = (const __half2*)&u;
            #pragma unroll
            for (int j = 0; j < 4; j++) acc[r * 4 + j] = __half22float2(h[j]);
        }
    }

    int nbr[SAMP];
    #pragma unroll
    for (int s = 0; s < SAMP; s++) nbr[s] = nb[node * SAMP + s];

    #pragma unroll
    for (int s = 0; s < SAMP; s++) {
        const uint4* p = (const uint4*)(z + (size_t)nbr[s] * DIM);
        #pragma unroll
        for (int r = 0; r < 4; r++) {
            uint4 u = p[r * 4 + q];
            const __half2* h = (const __half2*)&u;
            #pragma unroll
            for (int j = 0; j < 4; j++) {
                float2 f = __half22float2(h[j]);
                acc[r * 4 + j].x += f.x;
                acc[r * 4 + j].y += f.y;
            }
        }
    }

    const float inv17 = 1.0f / (float)(SAMP + 1);
    float ss = 0.0f;
    #pragma unroll
    for (int i = 0; i < 16; i++) {
        float2 v = acc[i];
        v.x = fmaxf(v.x * inv17, 0.0f);
        v.y = fmaxf(v.y * inv17, 0.0f);
        acc[i] = v;
        ss += v.x * v.x + v.y * v.y;
    }
    // reduce across the 4 threads of this node (quad-aligned lanes)
    ss += __shfl_xor_sync(0xffffffffu, ss, 1);
    ss += __shfl_xor_sync(0xffffffffu, ss, 2);

    const float inv = 1.0f / fmaxf(sqrtf(ss), 1e-12f);
    if (valid) {
        float4* o = (float4*)(out + (size_t)node * DIM);
        #pragma unroll
        for (int r = 0; r < 4; r++) {
            int chunk = r * 4 + q;          // 8-dim chunk
            float4 v0 = make_float4(acc[r*4+0].x * inv, acc[r*4+0].y * inv,
                                    acc[r*4+1].x * inv, acc[r*4+1].y * inv);
            float4 v1 = make_float4(acc[r*4+2].x * inv, acc[r*4+2].y * inv,
                                    acc[r*4+3].x * inv, acc[r*4+3].y * inv);
            o[chunk * 2 + 0] = v0;
            o[chunk * 2 + 1] = v1;
        }
    }
}

// ---------------------------------------------------------------------------
extern "C" void kernel_launch(void* const* d_in, const int* in_sizes, int n_in,
                              void* d_out, int out_size)
{
    const float* feat = (const float*)d_in[0];   // [N, 64]
    const float* wf   = (const float*)d_in[1];   // [128, 64]
    const float* w1   = (const float*)d_in[2];   // [128, 128]
    const float* w2   = (const float*)d_in[3];   // [128, 128]
    const int*   n1   = (const int*)d_in[4];     // [N, 16]
    const int*   n2   = (const int*)d_in[5];     // [N, 16]
    float* out = (float*)d_out;                  // [N, 128]

    void *pz = nullptr, *px1 = nullptr, *pwc = nullptr;
    cudaGetSymbolAddress(&pz, g_z);
    cudaGetSymbolAddress(&px1, g_x1);
    cudaGetSymbolAddress(&pwc, g_wc);
    __half* z  = (__half*)pz;
    float*  x1 = (float*)px1;
    float*  wc = (float*)pwc;

    const size_t SM64  = (size_t)DIM * (FIN / 2) * sizeof(uint2);   // 32 KB
    const size_t SM128 = (size_t)DIM * (DIM / 2) * sizeof(uint2);   // 64 KB
    cudaFuncSetAttribute(gemm_split<FIN>, cudaFuncAttributeMaxDynamicSharedMemorySize,
                         (int)SM64);
    cudaFuncSetAttribute(gemm_split<DIM>, cudaFuncAttributeMaxDynamicSharedMemorySize,
                         (int)SM128);

    const int gemm_grid = (NNODES + 127) / 128;   // 782
    const int gn_grid   = (NNODES + 63) / 64;     // 1563

    // wc = w1 @ wf  (folds layer-1 GEMM into the feature GEMM)
    wc_kernel<<<32, 256>>>(w1, wf, wc);
    // z1 = feat @ wc^T   (fp16 out)
    gemm_split<FIN><<<gemm_grid, 256, SM64>>>(feat, wc, z, NNODES);
    // x1 = normalize(relu(agg(z1)))
    gathernorm<<<gn_grid, 256>>>(z, n1, x1);
    // z2 = x1 @ w2^T     (fp16 out)
    gemm_split<DIM><<<gemm_grid, 256, SM128>>>(x1, w2, z, NNODES);
    // out = normalize(relu(agg(z2)))
    gathernorm<<<gn_grid, 256>>>(z, n2, out);
}

// round 6
// speedup vs baseline: 2.9407x; 1.0482x over previous
#include <cuda_runtime.h>
#include <cuda_fp16.h>

#define NNODES 100000
#define DIM 128
#define FIN 64
#define SAMP 16

// Scratch (module-load allocated; no runtime alloc)
__device__ __half g_z     [(size_t)NNODES * DIM];   // pre-aggregation embeddings
__device__ __half g_x1h   [(size_t)NNODES * DIM];   // layer-1 output (fp16)
__device__ __half g_feat16[(size_t)NNODES * FIN];   // fp16 copy of input features
__device__ float  g_wc    [DIM * FIN];              // folded w1 @ wf

// ---------------------------------------------------------------------------
// wc = w1 @ wf   [128,128]@[128,64] -> [128,64]
// ---------------------------------------------------------------------------
__global__ void wc_kernel(const float* __restrict__ w1,
                          const float* __restrict__ wf,
                          float* __restrict__ wc)
{
    int idx = blockIdx.x * 256 + threadIdx.x;      // 8192 outputs
    if (idx >= DIM * FIN) return;
    int i = idx >> 6, j = idx & 63;
    float s = 0.0f;
    #pragma unroll 8
    for (int t = 0; t < DIM; t++)
        s = fmaf(w1[i * DIM + t], wf[t * FIN + j], s);
    wc[i * FIN + j] = s;
}

// ---------------------------------------------------------------------------
// feat fp32 -> fp16 (vectorized)
// ---------------------------------------------------------------------------
__global__ void to_half_kernel(const float* __restrict__ in,
                               __half* __restrict__ out, int n4)
{
    int i = blockIdx.x * 256 + threadIdx.x;        // n4 = elems/4
    if (i >= n4) return;
    float4 f = ((const float4*)in)[i];
    __half2 h0 = __float22half2_rn(make_float2(f.x, f.y));
    __half2 h1 = __float22half2_rn(make_float2(f.z, f.w));
    ((uint2*)out)[i] = make_uint2(*(unsigned*)&h0, *(unsigned*)&h1);
}

// ---------------------------------------------------------------------------
// Dense GEMM: C[nrows,128](fp16) = A[nrows,K](fp16) @ W[128,K]^T(fp32)
// W split to fp16 hi+lo (2-term: A*hi + A*lo) on mma.sync.m16n8k16.f16.
// Block: 256 thr (8 warps); warp = 16 rows x 128 cols (nt=16). 2 CTAs/SM.
// W staged in smem as interleaved uint2{hi2,lo2}, XOR bank swizzle, LDS.64.
// ---------------------------------------------------------------------------
#define MMA_F16(D, A0,A1,A2,A3, B0,B1)                                       \
    asm volatile("mma.sync.aligned.m16n8k16.row.col.f32.f16.f16.f32 "        \
                 "{%0,%1,%2,%3},{%4,%5,%6,%7},{%8,%9},{%0,%1,%2,%3};"        \
                 : "+f"(D[0]), "+f"(D[1]), "+f"(D[2]), "+f"(D[3])            \
                 : "r"(A0), "r"(A1), "r"(A2), "r"(A3), "r"(B0), "r"(B1))

template<int K>
__global__ __launch_bounds__(256, 2)
void gemm_wsplit(const __half* __restrict__ A,
                 const float* __restrict__ W,
                 __half* __restrict__ C, int nrows)
{
    constexpr int K2 = K / 2;                       // packed half2 cols
    extern __shared__ uint2 WB[];                   // [DIM][K2]  {hi2, lo2}

    const int tid = threadIdx.x;

    // Stage W: fp16 hi + fp16 residual-lo, interleaved, XOR bank swizzle
    for (int idx = tid; idx < DIM * K2; idx += 256) {
        int n = idx / K2, c2 = idx % K2;
        float2 f = *(const float2*)&W[n * K + 2 * c2];
        __half2 h = __float22half2_rn(f);
        float2 hf = __half22float2(h);
        __half2 l = __float22half2_rn(make_float2(f.x - hf.x, f.y - hf.y));
        int sc = c2 ^ ((n & 7) << 2);
        WB[n * K2 + sc] = make_uint2(*(unsigned*)&h, *(unsigned*)&l);
    }
    __syncthreads();

    const int warp = tid >> 5, lane = tid & 31;
    const int g = lane >> 2, c = lane & 3;

    long mrow = (long)blockIdx.x * 128 + warp * 16 + g;
    long r0 = mrow     < nrows ? mrow     : nrows - 1;
    long r1 = mrow + 8 < nrows ? mrow + 8 : nrows - 1;
    const __half* A0 = A + r0 * K;
    const __half* A1 = A + r1 * K;

    float d[16][4];
    #pragma unroll
    for (int nt = 0; nt < 16; nt++)
        #pragma unroll
        for (int q = 0; q < 4; q++) d[nt][q] = 0.0f;

    const int gsw = g << 2;

    #pragma unroll 2
    for (int ks = 0; ks < K / 16; ks++) {
        const int k = ks * 16;
        // A fragments: direct packed-half2 loads, no conversion
        unsigned a0 = *(const unsigned*)&A0[k + 2 * c];
        unsigned a1 = *(const unsigned*)&A1[k + 2 * c];
        unsigned a2 = *(const unsigned*)&A0[k + 2 * c + 8];
        unsigned a3 = *(const unsigned*)&A1[k + 2 * c + 8];

        const int k2 = ks * 8;
        const int col0 = (k2 + c)     ^ gsw;
        const int col1 = (k2 + c + 4) ^ gsw;

        #pragma unroll
        for (int nt = 0; nt < 16; nt++) {
            const uint2* Wrow = WB + (size_t)(nt * 8 + g) * K2;
            uint2 b0 = Wrow[col0];
            uint2 b1 = Wrow[col1];
            MMA_F16(d[nt], a0, a1, a2, a3, b0.x, b1.x);   // A * W_hi
            MMA_F16(d[nt], a0, a1, a2, a3, b0.y, b1.y);   // A * W_lo
        }
    }

    // Epilogue: fp16 output
    long wr0 = (long)blockIdx.x * 128 + warp * 16 + g;
    long wr1 = wr0 + 8;
    #pragma unroll
    for (int nt = 0; nt < 16; nt++) {
        int col = nt * 8 + 2 * c;
        if (wr0 < nrows) {
            __half2 h = __float22half2_rn(make_float2(d[nt][0], d[nt][1]));
            *(__half2*)&C[wr0 * DIM + col] = h;
        }
        if (wr1 < nrows) {
            __half2 h = __float22half2_rn(make_float2(d[nt][2], d[nt][3]));
            *(__half2*)&C[wr1 * DIM + col] = h;
        }
    }
}

// ---------------------------------------------------------------------------
// gathernorm: out[n] = normalize(relu((z[n] + sum_s z[nb[n,s]]) / 17))
// z fp16 (256B/row). 4 threads/node, 64 nodes/block. LTS-bound gather.
// HALF_OUT: write fp16 (layer-1 x1) vs fp32 (final out).
// ---------------------------------------------------------------------------
template<bool HALF_OUT>
__global__ __launch_bounds__(256)
void gathernorm(const __half* __restrict__ z,
                const int*    __restrict__ nb,
                void*         __restrict__ outv)
{
    const int tid = threadIdx.x;
    const int m = tid >> 2;          // node in block
    const int q = tid & 3;           // quarter
    int node = blockIdx.x * 64 + m;
    const bool valid = node < NNODES;
    if (!valid) node = NNODES - 1;

    float2 acc[16];
    {
        const uint4* zr = (const uint4*)(z + (size_t)node * DIM);
        #pragma unroll
        for (int r = 0; r < 4; r++) {
            uint4 u = zr[r * 4 + q];
            const __half2* h = (const __half2*)&u;
            #pragma unroll
            for (int j = 0; j < 4; j++) acc[r * 4 + j] = __half22float2(h[j]);
        }
    }

    int nbr[SAMP];
    #pragma unroll
    for (int s = 0; s < SAMP; s++) nbr[s] = nb[node * SAMP + s];

    #pragma unroll
    for (int s = 0; s < SAMP; s++) {
        const uint4* p = (const uint4*)(z + (size_t)nbr[s] * DIM);
        #pragma unroll
        for (int r = 0; r < 4; r++) {
            uint4 u = p[r * 4 + q];
            const __half2* h = (const __half2*)&u;
            #pragma unroll
            for (int j = 0; j < 4; j++) {
                float2 f = __half22float2(h[j]);
                acc[r * 4 + j].x += f.x;
                acc[r * 4 + j].y += f.y;
            }
        }
    }

    const float inv17 = 1.0f / (float)(SAMP + 1);
    float ss = 0.0f;
    #pragma unroll
    for (int i = 0; i < 16; i++) {
        float2 v = acc[i];
        v.x = fmaxf(v.x * inv17, 0.0f);
        v.y = fmaxf(v.y * inv17, 0.0f);
        acc[i] = v;
        ss += v.x * v.x + v.y * v.y;
    }
    ss += __shfl_xor_sync(0xffffffffu, ss, 1);
    ss += __shfl_xor_sync(0xffffffffu, ss, 2);

    const float inv = 1.0f / fmaxf(sqrtf(ss), 1e-12f);
    if (valid) {
        if (HALF_OUT) {
            uint4* o = (uint4*)((__half*)outv + (size_t)node * DIM);
            #pragma unroll
            for (int r = 0; r < 4; r++) {
                __half2 h[4];
                #pragma unroll
                for (int j = 0; j < 4; j++)
                    h[j] = __float22half2_rn(make_float2(acc[r*4+j].x * inv,
                                                         acc[r*4+j].y * inv));
                o[r * 4 + q] = make_uint4(*(unsigned*)&h[0], *(unsigned*)&h[1],
                                          *(unsigned*)&h[2], *(unsigned*)&h[3]);
            }
        } else {
            float4* o = (float4*)((float*)outv + (size_t)node * DIM);
            #pragma unroll
            for (int r = 0; r < 4; r++) {
                int chunk = r * 4 + q;
                float4 v0 = make_float4(acc[r*4+0].x * inv, acc[r*4+0].y * inv,
                                        acc[r*4+1].x * inv, acc[r*4+1].y * inv);
                float4 v1 = make_float4(acc[r*4+2].x * inv, acc[r*4+2].y * inv,
                                        acc[r*4+3].x * inv, acc[r*4+3].y * inv);
                o[chunk * 2 + 0] = v0;
                o[chunk * 2 + 1] = v1;
            }
        }
    }
}

// ---------------------------------------------------------------------------
extern "C" void kernel_launch(void* const* d_in, const int* in_sizes, int n_in,
                              void* d_out, int out_size)
{
    const float* feat = (const float*)d_in[0];   // [N, 64]
    const float* wf   = (const float*)d_in[1];   // [128, 64]
    const float* w1   = (const float*)d_in[2];   // [128, 128]
    const float* w2   = (const float*)d_in[3];   // [128, 128]
    const int*   n1   = (const int*)d_in[4];     // [N, 16]
    const int*   n2   = (const int*)d_in[5];     // [N, 16]
    float* out = (float*)d_out;                  // [N, 128]

    void *pz = nullptr, *px1 = nullptr, *pwc = nullptr, *pf16 = nullptr;
    cudaGetSymbolAddress(&pz, g_z);
    cudaGetSymbolAddress(&px1, g_x1h);
    cudaGetSymbolAddress(&pwc, g_wc);
    cudaGetSymbolAddress(&pf16, g_feat16);
    __half* z   = (__half*)pz;
    __half* x1h = (__half*)px1;
    float*  wc  = (float*)pwc;
    __half* f16 = (__half*)pf16;

    const size_t SM64  = (size_t)DIM * (FIN / 2) * sizeof(uint2);   // 32 KB
    const size_t SM128 = (size_t)DIM * (DIM / 2) * sizeof(uint2);   // 64 KB
    cudaFuncSetAttribute(gemm_wsplit<FIN>, cudaFuncAttributeMaxDynamicSharedMemorySize,
                         (int)SM64);
    cudaFuncSetAttribute(gemm_wsplit<DIM>, cudaFuncAttributeMaxDynamicSharedMemorySize,
                         (int)SM128);

    const int gemm_grid = (NNODES + 127) / 128;     // 782
    const int gn_grid   = (NNODES + 63) / 64;       // 1563
    const int th_grid   = (NNODES * FIN / 4 + 255) / 256;

    // wc = w1 @ wf  (folds layer-1 GEMM into the feature GEMM)
    wc_kernel<<<32, 256>>>(w1, wf, wc);
    // feat -> fp16
    to_half_kernel<<<th_grid, 256>>>(feat, f16, NNODES * FIN / 4);
    // z1 = feat16 @ wc^T   (fp16 out)
    gemm_wsplit<FIN><<<gemm_grid, 256, SM64>>>(f16, wc, z, NNODES);
    // x1 = normalize(relu(agg(z1)))  -> fp16
    gathernorm<true><<<gn_grid, 256>>>(z, n1, x1h);
    // z2 = x1 @ w2^T       (fp16 out)
    gemm_wsplit<DIM><<<gemm_grid, 256, SM128>>>(x1h, w2, z, NNODES);
    // out = normalize(relu(agg(z2))) -> fp32
    gathernorm<false><<<gn_grid, 256>>>(z, n2, out);
}

// round 7
// speedup vs baseline: 2.9760x; 1.0120x over previous
#include <cuda_runtime.h>
#include <cuda_fp16.h>

#define NNODES 100000
#define DIM 128
#define FIN 64
#define SAMP 16

// Scratch (module-load allocated; no runtime alloc)
__device__ __half g_z     [(size_t)NNODES * DIM];   // pre-aggregation embeddings
__device__ __half g_x1h   [(size_t)NNODES * DIM];   // layer-1 output (fp16)
__device__ __half g_feat16[(size_t)NNODES * FIN];   // fp16 copy of input features
__device__ float  g_wc    [DIM * FIN];              // folded w1 @ wf

// ---------------------------------------------------------------------------
// wc = w1 @ wf   [128,128]@[128,64] -> [128,64]
// ---------------------------------------------------------------------------
__global__ void wc_kernel(const float* __restrict__ w1,
                          const float* __restrict__ wf,
                          float* __restrict__ wc)
{
    int idx = blockIdx.x * 256 + threadIdx.x;      // 8192 outputs
    if (idx >= DIM * FIN) return;
    int i = idx >> 6, j = idx & 63;
    float s = 0.0f;
    #pragma unroll 8
    for (int t = 0; t < DIM; t++)
        s = fmaf(w1[i * DIM + t], wf[t * FIN + j], s);
    wc[i * FIN + j] = s;
}

// ---------------------------------------------------------------------------
// feat fp32 -> fp16 (vectorized)
// ---------------------------------------------------------------------------
__global__ void to_half_kernel(const float* __restrict__ in,
                               __half* __restrict__ out, int n4)
{
    int i = blockIdx.x * 256 + threadIdx.x;        // n4 = elems/4
    if (i >= n4) return;
    float4 f = ((const float4*)in)[i];
    __half2 h0 = __float22half2_rn(make_float2(f.x, f.y));
    __half2 h1 = __float22half2_rn(make_float2(f.z, f.w));
    ((uint2*)out)[i] = make_uint2(*(unsigned*)&h0, *(unsigned*)&h1);
}

// ---------------------------------------------------------------------------
// Dense GEMM: C[nrows,128](fp16) = A[nrows,K](fp16) @ W[128,K]^T(fp32)
// W split to fp16 hi+lo (2-term: A*hi + A*lo) on mma.sync.m16n8k16.f16.
// Block: 256 thr (8 warps); warp = 16 rows x 128 cols (nt=16). 2 CTAs/SM.
// W staged in smem as interleaved uint2{hi2,lo2}, XOR bank swizzle, LDS.64.
// ---------------------------------------------------------------------------
#define MMA_F16(D, A0,A1,A2,A3, B0,B1)                                       \
    asm volatile("mma.sync.aligned.m16n8k16.row.col.f32.f16.f16.f32 "        \
                 "{%0,%1,%2,%3},{%4,%5,%6,%7},{%8,%9},{%0,%1,%2,%3};"        \
                 : "+f"(D[0]), "+f"(D[1]), "+f"(D[2]), "+f"(D[3])            \
                 : "r"(A0), "r"(A1), "r"(A2), "r"(A3), "r"(B0), "r"(B1))

template<int K>
__global__ __launch_bounds__(256, 2)
void gemm_wsplit(const __half* __restrict__ A,
                 const float* __restrict__ W,
                 __half* __restrict__ C, int nrows)
{
    constexpr int K2 = K / 2;                       // packed half2 cols
    extern __shared__ uint2 WB[];                   // [DIM][K2]  {hi2, lo2}

    const int tid = threadIdx.x;

    // Stage W: fp16 hi + fp16 residual-lo, interleaved, XOR bank swizzle
    for (int idx = tid; idx < DIM * K2; idx += 256) {
        int n = idx / K2, c2 = idx % K2;
        float2 f = *(const float2*)&W[n * K + 2 * c2];
        __half2 h = __float22half2_rn(f);
        float2 hf = __half22float2(h);
        __half2 l = __float22half2_rn(make_float2(f.x - hf.x, f.y - hf.y));
        int sc = c2 ^ ((n & 7) << 2);
        WB[n * K2 + sc] = make_uint2(*(unsigned*)&h, *(unsigned*)&l);
    }
    __syncthreads();

    const int warp = tid >> 5, lane = tid & 31;
    const int g = lane >> 2, c = lane & 3;

    long mrow = (long)blockIdx.x * 128 + warp * 16 + g;
    long r0 = mrow     < nrows ? mrow     : nrows - 1;
    long r1 = mrow + 8 < nrows ? mrow + 8 : nrows - 1;
    const __half* A0 = A + r0 * K;
    const __half* A1 = A + r1 * K;

    float d[16][4];
    #pragma unroll
    for (int nt = 0; nt < 16; nt++)
        #pragma unroll
        for (int q = 0; q < 4; q++) d[nt][q] = 0.0f;

    const int gsw = g << 2;

    #pragma unroll 2
    for (int ks = 0; ks < K / 16; ks++) {
        const int k = ks * 16;
        // A fragments: direct packed-half2 loads, no conversion
        unsigned a0 = *(const unsigned*)&A0[k + 2 * c];
        unsigned a1 = *(const unsigned*)&A1[k + 2 * c];
        unsigned a2 = *(const unsigned*)&A0[k + 2 * c + 8];
        unsigned a3 = *(const unsigned*)&A1[k + 2 * c + 8];

        const int k2 = ks * 8;
        const int col0 = (k2 + c)     ^ gsw;
        const int col1 = (k2 + c + 4) ^ gsw;

        #pragma unroll
        for (int nt = 0; nt < 16; nt++) {
            const uint2* Wrow = WB + (size_t)(nt * 8 + g) * K2;
            uint2 b0 = Wrow[col0];
            uint2 b1 = Wrow[col1];
            MMA_F16(d[nt], a0, a1, a2, a3, b0.x, b1.x);   // A * W_hi
            MMA_F16(d[nt], a0, a1, a2, a3, b0.y, b1.y);   // A * W_lo
        }
    }

    // Epilogue: fp16 output
    long wr0 = (long)blockIdx.x * 128 + warp * 16 + g;
    long wr1 = wr0 + 8;
    #pragma unroll
    for (int nt = 0; nt < 16; nt++) {
        int col = nt * 8 + 2 * c;
        if (wr0 < nrows) {
            __half2 h = __float22half2_rn(make_float2(d[nt][0], d[nt][1]));
            *(__half2*)&C[wr0 * DIM + col] = h;
        }
        if (wr1 < nrows) {
            __half2 h = __float22half2_rn(make_float2(d[nt][2], d[nt][3]));
            *(__half2*)&C[wr1 * DIM + col] = h;
        }
    }
}

// ---------------------------------------------------------------------------
// gathernorm: out[n] = normalize(relu((z[n] + sum_s z[nb[n,s]]) / 17))
// z fp16 (256B/row). 4 threads/node, 64 nodes/block.
// Accumulate in fp16 (HADD2) — 4x fewer fma-pipe ops than cvt+fadd.
// ---------------------------------------------------------------------------
template<bool HALF_OUT>
__global__ __launch_bounds__(256)
void gathernorm(const __half* __restrict__ z,
                const int*    __restrict__ nb,
                void*         __restrict__ outv)
{
    const int tid = threadIdx.x;
    const int m = tid >> 2;          // node in block
    const int q = tid & 3;           // quarter
    int node = blockIdx.x * 64 + m;
    const bool valid = node < NNODES;
    if (!valid) node = NNODES - 1;

    // fp16 accumulators: acc[r*4+j] = half2 pair j of 16B chunk (r*4+q)
    __half2 acc[16];
    {
        const uint4* zr = (const uint4*)(z + (size_t)node * DIM);
        #pragma unroll
        for (int r = 0; r < 4; r++) {
            uint4 u = zr[r * 4 + q];
            const __half2* h = (const __half2*)&u;
            #pragma unroll
            for (int j = 0; j < 4; j++) acc[r * 4 + j] = h[j];
        }
    }

    int nbr[SAMP];
    #pragma unroll
    for (int s = 0; s < SAMP; s++) nbr[s] = nb[node * SAMP + s];

    #pragma unroll
    for (int s = 0; s < SAMP; s++) {
        const uint4* p = (const uint4*)(z + (size_t)nbr[s] * DIM);
        #pragma unroll
        for (int r = 0; r < 4; r++) {
            uint4 u = p[r * 4 + q];
            const __half2* h = (const __half2*)&u;
            #pragma unroll
            for (int j = 0; j < 4; j++)
                acc[r * 4 + j] = __hadd2(acc[r * 4 + j], h[j]);
        }
    }

    // Convert once, then scale + relu + norm in fp32
    const float inv17 = 1.0f / (float)(SAMP + 1);
    float2 fa[16];
    float ss = 0.0f;
    #pragma unroll
    for (int i = 0; i < 16; i++) {
        float2 v = __half22float2(acc[i]);
        v.x = fmaxf(v.x * inv17, 0.0f);
        v.y = fmaxf(v.y * inv17, 0.0f);
        fa[i] = v;
        ss += v.x * v.x + v.y * v.y;
    }
    ss += __shfl_xor_sync(0xffffffffu, ss, 1);
    ss += __shfl_xor_sync(0xffffffffu, ss, 2);

    const float inv = 1.0f / fmaxf(sqrtf(ss), 1e-12f);
    if (valid) {
        if (HALF_OUT) {
            uint4* o = (uint4*)((__half*)outv + (size_t)node * DIM);
            #pragma unroll
            for (int r = 0; r < 4; r++) {
                __half2 h[4];
                #pragma unroll
                for (int j = 0; j < 4; j++)
                    h[j] = __float22half2_rn(make_float2(fa[r*4+j].x * inv,
                                                         fa[r*4+j].y * inv));
                o[r * 4 + q] = make_uint4(*(unsigned*)&h[0], *(unsigned*)&h[1],
                                          *(unsigned*)&h[2], *(unsigned*)&h[3]);
            }
        } else {
            float4* o = (float4*)((float*)outv + (size_t)node * DIM);
            #pragma unroll
            for (int r = 0; r < 4; r++) {
                int chunk = r * 4 + q;
                float4 v0 = make_float4(fa[r*4+0].x * inv, fa[r*4+0].y * inv,
                                        fa[r*4+1].x * inv, fa[r*4+1].y * inv);
                float4 v1 = make_float4(fa[r*4+2].x * inv, fa[r*4+2].y * inv,
                                        fa[r*4+3].x * inv, fa[r*4+3].y * inv);
                o[chunk * 2 + 0] = v0;
                o[chunk * 2 + 1] = v1;
            }
        }
    }
}

// ---------------------------------------------------------------------------
extern "C" void kernel_launch(void* const* d_in, const int* in_sizes, int n_in,
                              void* d_out, int out_size)
{
    const float* feat = (const float*)d_in[0];   // [N, 64]
    const float* wf   = (const float*)d_in[1];   // [128, 64]
    const float* w1   = (const float*)d_in[2];   // [128, 128]
    const float* w2   = (const float*)d_in[3];   // [128, 128]
    const int*   n1   = (const int*)d_in[4];     // [N, 16]
    const int*   n2   = (const int*)d_in[5];     // [N, 16]
    float* out = (float*)d_out;                  // [N, 128]

    void *pz = nullptr, *px1 = nullptr, *pwc = nullptr, *pf16 = nullptr;
    cudaGetSymbolAddress(&pz, g_z);
    cudaGetSymbolAddress(&px1, g_x1h);
    cudaGetSymbolAddress(&pwc, g_wc);
    cudaGetSymbolAddress(&pf16, g_feat16);
    __half* z   = (__half*)pz;
    __half* x1h = (__half*)px1;
    float*  wc  = (float*)pwc;
    __half* f16 = (__half*)pf16;

    const size_t SM64  = (size_t)DIM * (FIN / 2) * sizeof(uint2);   // 32 KB
    const size_t SM128 = (size_t)DIM * (DIM / 2) * sizeof(uint2);   // 64 KB
    cudaFuncSetAttribute(gemm_wsplit<FIN>, cudaFuncAttributeMaxDynamicSharedMemorySize,
                         (int)SM64);
    cudaFuncSetAttribute(gemm_wsplit<DIM>, cudaFuncAttributeMaxDynamicSharedMemorySize,
                         (int)SM128);

    const int gemm_grid = (NNODES + 127) / 128;     // 782
    const int gn_grid   = (NNODES + 63) / 64;       // 1563
    const int th_grid   = (NNODES * FIN / 4 + 255) / 256;

    // wc = w1 @ wf  (folds layer-1 GEMM into the feature GEMM)
    wc_kernel<<<32, 256>>>(w1, wf, wc);
    // feat -> fp16
    to_half_kernel<<<th_grid, 256>>>(feat, f16, NNODES * FIN / 4);
    // z1 = feat16 @ wc^T   (fp16 out)
    gemm_wsplit<FIN><<<gemm_grid, 256, SM64>>>(f16, wc, z, NNODES);
    // x1 = normalize(relu(agg(z1)))  -> fp16
    gathernorm<true><<<gn_grid, 256>>>(z, n1, x1h);
    // z2 = x1 @ w2^T       (fp16 out)
    gemm_wsplit<DIM><<<gemm_grid, 256, SM128>>>(x1h, w2, z, NNODES);
    // out = normalize(relu(agg(z2))) -> fp32
    gathernorm<false><<<gn_grid, 256>>>(z, n2, out);
}

// round 8
// speedup vs baseline: 3.2149x; 1.0803x over previous
#include <cuda_runtime.h>
#include <cuda_fp16.h>

#define NNODES 100000
#define DIM 128
#define FIN 64
#define SAMP 16

// Scratch (module-load allocated; no runtime alloc)
__device__ __half g_z     [(size_t)NNODES * DIM];   // pre-aggregation embeddings
__device__ __half g_x1h   [(size_t)NNODES * DIM];   // layer-1 output (fp16)
__device__ __half g_feat16[(size_t)NNODES * FIN];   // fp16 copy of input features
__device__ float  g_wc    [DIM * FIN];              // folded w1 @ wf

// ---------------------------------------------------------------------------
// wc = w1 @ wf   [128,128]@[128,64] -> [128,64]
// ---------------------------------------------------------------------------
__global__ void wc_kernel(const float* __restrict__ w1,
                          const float* __restrict__ wf,
                          float* __restrict__ wc)
{
    int idx = blockIdx.x * 256 + threadIdx.x;      // 8192 outputs
    if (idx >= DIM * FIN) return;
    int i = idx >> 6, j = idx & 63;
    float s = 0.0f;
    #pragma unroll 8
    for (int t = 0; t < DIM; t++)
        s = fmaf(w1[i * DIM + t], wf[t * FIN + j], s);
    wc[i * FIN + j] = s;
}

// ---------------------------------------------------------------------------
// feat fp32 -> fp16 (vectorized)
// ---------------------------------------------------------------------------
__global__ void to_half_kernel(const float* __restrict__ in,
                               __half* __restrict__ out, int n4)
{
    int i = blockIdx.x * 256 + threadIdx.x;        // n4 = elems/4
    if (i >= n4) return;
    float4 f = ((const float4*)in)[i];
    __half2 h0 = __float22half2_rn(make_float2(f.x, f.y));
    __half2 h1 = __float22half2_rn(make_float2(f.z, f.w));
    ((uint2*)out)[i] = make_uint2(*(unsigned*)&h0, *(unsigned*)&h1);
}

// ---------------------------------------------------------------------------
// Dense GEMM: C[nrows,128](fp16) = A[nrows,K](fp16) @ W[128,K]^T(fp32)
// W split to fp16 hi+lo (2-term: A*hi + A*lo) on mma.sync.m16n8k16.f16.
// Block: 256 thr (8 warps); warp = 16 rows x 128 cols (nt=16). 2 CTAs/SM.
// ---------------------------------------------------------------------------
#define MMA_F16(D, A0,A1,A2,A3, B0,B1)                                       \
    asm volatile("mma.sync.aligned.m16n8k16.row.col.f32.f16.f16.f32 "        \
                 "{%0,%1,%2,%3},{%4,%5,%6,%7},{%8,%9},{%0,%1,%2,%3};"        \
                 : "+f"(D[0]), "+f"(D[1]), "+f"(D[2]), "+f"(D[3])            \
                 : "r"(A0), "r"(A1), "r"(A2), "r"(A3), "r"(B0), "r"(B1))

template<int K>
__global__ __launch_bounds__(256, 2)
void gemm_wsplit(const __half* __restrict__ A,
                 const float* __restrict__ W,
                 __half* __restrict__ C, int nrows)
{
    constexpr int K2 = K / 2;                       // packed half2 cols
    extern __shared__ uint2 WB[];                   // [DIM][K2]  {hi2, lo2}

    const int tid = threadIdx.x;

    // Stage W: fp16 hi + fp16 residual-lo, interleaved, XOR bank swizzle
    for (int idx = tid; idx < DIM * K2; idx += 256) {
        int n = idx / K2, c2 = idx % K2;
        float2 f = *(const float2*)&W[n * K + 2 * c2];
        __half2 h = __float22half2_rn(f);
        float2 hf = __half22float2(h);
        __half2 l = __float22half2_rn(make_float2(f.x - hf.x, f.y - hf.y));
        int sc = c2 ^ ((n & 7) << 2);
        WB[n * K2 + sc] = make_uint2(*(unsigned*)&h, *(unsigned*)&l);
    }
    __syncthreads();

    const int warp = tid >> 5, lane = tid & 31;
    const int g = lane >> 2, c = lane & 3;

    long mrow = (long)blockIdx.x * 128 + warp * 16 + g;
    long r0 = mrow     < nrows ? mrow     : nrows - 1;
    long r1 = mrow + 8 < nrows ? mrow + 8 : nrows - 1;
    const __half* A0 = A + r0 * K;
    const __half* A1 = A + r1 * K;

    float d[16][4];
    #pragma unroll
    for (int nt = 0; nt < 16; nt++)
        #pragma unroll
        for (int q = 0; q < 4; q++) d[nt][q] = 0.0f;

    const int gsw = g << 2;

    #pragma unroll 2
    for (int ks = 0; ks < K / 16; ks++) {
        const int k = ks * 16;
        unsigned a0 = *(const unsigned*)&A0[k + 2 * c];
        unsigned a1 = *(const unsigned*)&A1[k + 2 * c];
        unsigned a2 = *(const unsigned*)&A0[k + 2 * c + 8];
        unsigned a3 = *(const unsigned*)&A1[k + 2 * c + 8];

        const int k2 = ks * 8;
        const int col0 = (k2 + c)     ^ gsw;
        const int col1 = (k2 + c + 4) ^ gsw;

        #pragma unroll
        for (int nt = 0; nt < 16; nt++) {
            const uint2* Wrow = WB + (size_t)(nt * 8 + g) * K2;
            uint2 b0 = Wrow[col0];
            uint2 b1 = Wrow[col1];
            MMA_F16(d[nt], a0, a1, a2, a3, b0.x, b1.x);   // A * W_hi
            MMA_F16(d[nt], a0, a1, a2, a3, b0.y, b1.y);   // A * W_lo
        }
    }

    long wr0 = (long)blockIdx.x * 128 + warp * 16 + g;
    long wr1 = wr0 + 8;
    #pragma unroll
    for (int nt = 0; nt < 16; nt++) {
        int col = nt * 8 + 2 * c;
        if (wr0 < nrows) {
            __half2 h = __float22half2_rn(make_float2(d[nt][0], d[nt][1]));
            *(__half2*)&C[wr0 * DIM + col] = h;
        }
        if (wr1 < nrows) {
            __half2 h = __float22half2_rn(make_float2(d[nt][2], d[nt][3]));
            *(__half2*)&C[wr1 * DIM + col] = h;
        }
    }
}

// ---------------------------------------------------------------------------
// gathernorm: out[n] = normalize(relu((z[n] + sum_s z[nb[n,s]]) / 17))
// 8 lanes/node (lane o loads 16B chunks o and o+8): every LDG.128 warp
// instruction covers 4 FULL 128B lines -> no L1 wavefront inflation.
// Neighbors summed pairwise in fp16 (1 HADD2/elem), pair-sums accumulated fp32.
// ---------------------------------------------------------------------------
template<bool HALF_OUT>
__global__ __launch_bounds__(256)
void gathernorm(const __half* __restrict__ z,
                const int*    __restrict__ nb,
                void*         __restrict__ outv)
{
    const int tid = threadIdx.x;
    const int m = tid >> 3;          // node in block (0..31)
    const int o = tid & 7;           // 16B chunk within each 128B line
    int node = blockIdx.x * 32 + m;
    const bool valid = node < NNODES;
    if (!valid) node = NNODES - 1;

    // fa[0..3] = chunk o (half2 pairs), fa[4..7] = chunk o+8
    float2 fa[8];
    {
        const uint4* zr = (const uint4*)(z + (size_t)node * DIM);
        uint4 u0 = zr[o], u1 = zr[o + 8];
        const __half2* h0 = (const __half2*)&u0;
        const __half2* h1 = (const __half2*)&u1;
        #pragma unroll
        for (int j = 0; j < 4; j++) {
            fa[j]     = __half22float2(h0[j]);
            fa[4 + j] = __half22float2(h1[j]);
        }
    }

    int nbr[SAMP];
    #pragma unroll
    for (int s = 0; s < SAMP; s++) nbr[s] = nb[node * SAMP + s];

    #pragma unroll
    for (int s = 0; s < SAMP; s += 2) {
        const uint4* p0 = (const uint4*)(z + (size_t)nbr[s]     * DIM);
        const uint4* p1 = (const uint4*)(z + (size_t)nbr[s + 1] * DIM);
        uint4 a0 = p0[o], a1 = p0[o + 8];
        uint4 b0 = p1[o], b1 = p1[o + 8];
        const __half2* ha0 = (const __half2*)&a0;
        const __half2* hb0 = (const __half2*)&b0;
        const __half2* ha1 = (const __half2*)&a1;
        const __half2* hb1 = (const __half2*)&b1;
        #pragma unroll
        for (int j = 0; j < 4; j++) {
            float2 f0 = __half22float2(__hadd2(ha0[j], hb0[j]));
            float2 f1 = __half22float2(__hadd2(ha1[j], hb1[j]));
            fa[j].x     += f0.x;  fa[j].y     += f0.y;
            fa[4 + j].x += f1.x;  fa[4 + j].y += f1.y;
        }
    }

    const float inv17 = 1.0f / (float)(SAMP + 1);
    float ss = 0.0f;
    #pragma unroll
    for (int i = 0; i < 8; i++) {
        float2 v = fa[i];
        v.x = fmaxf(v.x * inv17, 0.0f);
        v.y = fmaxf(v.y * inv17, 0.0f);
        fa[i] = v;
        ss += v.x * v.x + v.y * v.y;
    }
    // reduce across the 8 lanes of this node
    ss += __shfl_xor_sync(0xffffffffu, ss, 1);
    ss += __shfl_xor_sync(0xffffffffu, ss, 2);
    ss += __shfl_xor_sync(0xffffffffu, ss, 4);

    const float inv = 1.0f / fmaxf(sqrtf(ss), 1e-12f);
    if (valid) {
        if (HALF_OUT) {
            uint4* orow = (uint4*)((__half*)outv + (size_t)node * DIM);
            __half2 h[8];
            #pragma unroll
            for (int i = 0; i < 8; i++)
                h[i] = __float22half2_rn(make_float2(fa[i].x * inv, fa[i].y * inv));
            orow[o]     = make_uint4(*(unsigned*)&h[0], *(unsigned*)&h[1],
                                     *(unsigned*)&h[2], *(unsigned*)&h[3]);
            orow[o + 8] = make_uint4(*(unsigned*)&h[4], *(unsigned*)&h[5],
                                     *(unsigned*)&h[6], *(unsigned*)&h[7]);
        } else {
            float4* orow = (float4*)((float*)outv + (size_t)node * DIM);
            // chunk o -> fp32 float4 indices 2o, 2o+1 ; chunk o+8 -> 2o+16, 2o+17
            orow[2 * o]      = make_float4(fa[0].x * inv, fa[0].y * inv,
                                           fa[1].x * inv, fa[1].y * inv);
            orow[2 * o + 1]  = make_float4(fa[2].x * inv, fa[2].y * inv,
                                           fa[3].x * inv, fa[3].y * inv);
            orow[2 * o + 16] = make_float4(fa[4].x * inv, fa[4].y * inv,
                                           fa[5].x * inv, fa[5].y * inv);
            orow[2 * o + 17] = make_float4(fa[6].x * inv, fa[6].y * inv,
                                           fa[7].x * inv, fa[7].y * inv);
        }
    }
}

// ---------------------------------------------------------------------------
extern "C" void kernel_launch(void* const* d_in, const int* in_sizes, int n_in,
                              void* d_out, int out_size)
{
    const float* feat = (const float*)d_in[0];   // [N, 64]
    const float* wf   = (const float*)d_in[1];   // [128, 64]
    const float* w1   = (const float*)d_in[2];   // [128, 128]
    const float* w2   = (const float*)d_in[3];   // [128, 128]
    const int*   n1   = (const int*)d_in[4];     // [N, 16]
    const int*   n2   = (const int*)d_in[5];     // [N, 16]
    float* out = (float*)d_out;                  // [N, 128]

    void *pz = nullptr, *px1 = nullptr, *pwc = nullptr, *pf16 = nullptr;
    cudaGetSymbolAddress(&pz, g_z);
    cudaGetSymbolAddress(&px1, g_x1h);
    cudaGetSymbolAddress(&pwc, g_wc);
    cudaGetSymbolAddress(&pf16, g_feat16);
    __half* z   = (__half*)pz;
    __half* x1h = (__half*)px1;
    float*  wc  = (float*)pwc;
    __half* f16 = (__half*)pf16;

    const size_t SM64  = (size_t)DIM * (FIN / 2) * sizeof(uint2);   // 32 KB
    const size_t SM128 = (size_t)DIM * (DIM / 2) * sizeof(uint2);   // 64 KB
    cudaFuncSetAttribute(gemm_wsplit<FIN>, cudaFuncAttributeMaxDynamicSharedMemorySize,
                         (int)SM64);
    cudaFuncSetAttribute(gemm_wsplit<DIM>, cudaFuncAttributeMaxDynamicSharedMemorySize,
                         (int)SM128);

    const int gemm_grid = (NNODES + 127) / 128;     // 782
    const int gn_grid   = (NNODES + 31) / 32;       // 3125
    const int th_grid   = (NNODES * FIN / 4 + 255) / 256;

    // wc = w1 @ wf  (folds layer-1 GEMM into the feature GEMM)
    wc_kernel<<<32, 256>>>(w1, wf, wc);
    // feat -> fp16
    to_half_kernel<<<th_grid, 256>>>(feat, f16, NNODES * FIN / 4);
    // z1 = feat16 @ wc^T   (fp16 out)
    gemm_wsplit<FIN><<<gemm_grid, 256, SM64>>>(f16, wc, z, NNODES);
    // x1 = normalize(relu(agg(z1)))  -> fp16
    gathernorm<true><<<gn_grid, 256>>>(z, n1, x1h);
    // z2 = x1 @ w2^T       (fp16 out)
    gemm_wsplit<DIM><<<gemm_grid, 256, SM128>>>(x1h, w2, z, NNODES);
    // out = normalize(relu(agg(z2))) -> fp32
    gathernorm<false><<<gn_grid, 256>>>(z, n2, out);
}

// round 10
// speedup vs baseline: 3.5374x; 1.1003x over previous
#include <cuda_runtime.h>
#include <cuda_fp16.h>

#define NNODES 100000
#define DIM 128
#define FIN 64
#define SAMP 16

// Scratch (module-load allocated; no runtime alloc)
__device__ __half g_z  [(size_t)NNODES * DIM];   // pre-aggregation embeddings
__device__ __half g_x1h[(size_t)NNODES * DIM];   // layer-1 output (fp16)
__device__ float  g_wc [DIM * FIN];              // folded w1 @ wf

// ---------------------------------------------------------------------------
// wc = w1 @ wf   [128,128]@[128,64] -> [128,64]
// ---------------------------------------------------------------------------
__global__ void wc_kernel(const float* __restrict__ w1,
                          const float* __restrict__ wf,
                          float* __restrict__ wc)
{
    int idx = blockIdx.x * 256 + threadIdx.x;      // 8192 outputs
    if (idx >= DIM * FIN) return;
    int i = idx >> 6, j = idx & 63;
    float s = 0.0f;
    #pragma unroll 8
    for (int t = 0; t < DIM; t++)
        s = fmaf(w1[i * DIM + t], wf[t * FIN + j], s);
    wc[i * FIN + j] = s;
}

// ---------------------------------------------------------------------------
// Dense GEMM: C[nrows,128](fp16) = A[nrows,K] @ W[128,K]^T(fp32)
// A is fp16 (AF32=false) or fp32 converted on the fly (AF32=true).
// W split to fp16 hi+lo (2-term) on mma.sync.m16n8k16.f16. 256 thr, 2 CTAs/SM.
// ---------------------------------------------------------------------------
#define MMA_F16(D, A0,A1,A2,A3, B0,B1)                                       \
    asm volatile("mma.sync.aligned.m16n8k16.row.col.f32.f16.f16.f32 "        \
                 "{%0,%1,%2,%3},{%4,%5,%6,%7},{%8,%9},{%0,%1,%2,%3};"        \
                 : "+f"(D[0]), "+f"(D[1]), "+f"(D[2]), "+f"(D[3])            \
                 : "r"(A0), "r"(A1), "r"(A2), "r"(A3), "r"(B0), "r"(B1))

template<int K, bool AF32>
__global__ __launch_bounds__(256, 2)
void gemm_wsplit(const void* __restrict__ Av,
                 const float* __restrict__ W,
                 __half* __restrict__ C, int nrows)
{
    constexpr int K2 = K / 2;                       // packed half2 cols
    extern __shared__ uint2 WB[];                   // [DIM][K2]  {hi2, lo2}

    const int tid = threadIdx.x;

    // Stage W: fp16 hi + fp16 residual-lo, interleaved, XOR bank swizzle
    for (int idx = tid; idx < DIM * K2; idx += 256) {
        int n = idx / K2, c2 = idx % K2;
        float2 f = *(const float2*)&W[n * K + 2 * c2];
        __half2 h = __float22half2_rn(f);
        float2 hf = __half22float2(h);
        __half2 l = __float22half2_rn(make_float2(f.x - hf.x, f.y - hf.y));
        int sc = c2 ^ ((n & 7) << 2);
        WB[n * K2 + sc] = make_uint2(*(unsigned*)&h, *(unsigned*)&l);
    }
    __syncthreads();

    const int warp = tid >> 5, lane = tid & 31;
    const int g = lane >> 2, c = lane & 3;

    long mrow = (long)blockIdx.x * 128 + warp * 16 + g;
    long r0 = mrow     < nrows ? mrow     : nrows - 1;
    long r1 = mrow + 8 < nrows ? mrow + 8 : nrows - 1;

    float d[16][4];
    #pragma unroll
    for (int nt = 0; nt < 16; nt++)
        #pragma unroll
        for (int q = 0; q < 4; q++) d[nt][q] = 0.0f;

    const int gsw = g << 2;

    #pragma unroll 2
    for (int ks = 0; ks < K / 16; ks++) {
        const int k = ks * 16;
        unsigned a0, a1, a2, a3;
        if constexpr (AF32) {
            const float* A0f = (const float*)Av + r0 * K;
            const float* A1f = (const float*)Av + r1 * K;
            __half2 h;
            h = __float22half2_rn(*(const float2*)&A0f[k + 2 * c]);     a0 = *(unsigned*)&h;
            h = __float22half2_rn(*(const float2*)&A1f[k + 2 * c]);     a1 = *(unsigned*)&h;
            h = __float22half2_rn(*(const float2*)&A0f[k + 2 * c + 8]); a2 = *(unsigned*)&h;
            h = __float22half2_rn(*(const float2*)&A1f[k + 2 * c + 8]); a3 = *(unsigned*)&h;
        } else {
            const __half* A0h = (const __half*)Av + r0 * K;
            const __half* A1h = (const __half*)Av + r1 * K;
            a0 = *(const unsigned*)&A0h[k + 2 * c];
            a1 = *(const unsigned*)&A1h[k + 2 * c];
            a2 = *(const unsigned*)&A0h[k + 2 * c + 8];
            a3 = *(const unsigned*)&A1h[k + 2 * c + 8];
        }

        const int k2 = ks * 8;
        const int col0 = (k2 + c)     ^ gsw;
        const int col1 = (k2 + c + 4) ^ gsw;

        #pragma unroll
        for (int nt = 0; nt < 16; nt++) {
            const uint2* Wrow = WB + (size_t)(nt * 8 + g) * K2;
            uint2 b0 = Wrow[col0];
            uint2 b1 = Wrow[col1];
            MMA_F16(d[nt], a0, a1, a2, a3, b0.x, b1.x);   // A * W_hi
            MMA_F16(d[nt], a0, a1, a2, a3, b0.y, b1.y);   // A * W_lo
        }
    }

    long wr0 = (long)blockIdx.x * 128 + warp * 16 + g;
    long wr1 = wr0 + 8;
    #pragma unroll
    for (int nt = 0; nt < 16; nt++) {
        int col = nt * 8 + 2 * c;
        if (wr0 < nrows) {
            __half2 h = __float22half2_rn(make_float2(d[nt][0], d[nt][1]));
            *(__half2*)&C[wr0 * DIM + col] = h;
        }
        if (wr1 < nrows) {
            __half2 h = __float22half2_rn(make_float2(d[nt][2], d[nt][3]));
            *(__half2*)&C[wr1 * DIM + col] = h;
        }
    }
}

// ---------------------------------------------------------------------------
// gathernorm: out[n] = normalize(relu((z[n] + sum_s z[nb[n,s]]) / 17))
// 16 lanes/node, lane o owns one 16B chunk (17 x LDG.128 per thread).
// Neighbors in 4 groups of 4: 2-level fp16 tree then one fp32 accumulate.
// ---------------------------------------------------------------------------
template<bool HALF_OUT>
__global__ __launch_bounds__(256)
void gathernorm(const __half* __restrict__ z,
                const int*    __restrict__ nb,
                void*         __restrict__ outv)
{
    const int tid = threadIdx.x;
    const int m = tid >> 4;          // node in block (0..15)
    const int o = tid & 15;          // 16B chunk of the row
    int node = blockIdx.x * 16 + m;
    const bool valid = node < NNODES;
    if (!valid) node = NNODES - 1;

    // self chunk
    float2 fa[4];
    {
        uint4 u = ((const uint4*)(z + (size_t)node * DIM))[o];
        const __half2* h = (const __half2*)&u;
        #pragma unroll
        for (int j = 0; j < 4; j++) fa[j] = __half22float2(h[j]);
    }

    const int4* nrow = (const int4*)(nb + node * SAMP);

    #pragma unroll
    for (int sp = 0; sp < 4; sp++) {
        int4 id = nrow[sp];
        uint4 ua = ((const uint4*)(z + (size_t)id.x * DIM))[o];
        uint4 ub = ((const uint4*)(z + (size_t)id.y * DIM))[o];
        uint4 uc = ((const uint4*)(z + (size_t)id.z * DIM))[o];
        uint4 ud = ((const uint4*)(z + (size_t)id.w * DIM))[o];
        const __half2* ha = (const __half2*)&ua;
        const __half2* hb = (const __half2*)&ub;
        const __half2* hc = (const __half2*)&uc;
        const __half2* hd = (const __half2*)&ud;
        #pragma unroll
        for (int j = 0; j < 4; j++) {
            __half2 t = __hadd2(__hadd2(ha[j], hb[j]), __hadd2(hc[j], hd[j]));
            float2 f = __half22float2(t);
            fa[j].x += f.x;
            fa[j].y += f.y;
        }
    }

    const float inv17 = 1.0f / (float)(SAMP + 1);
    float ss = 0.0f;
    #pragma unroll
    for (int j = 0; j < 4; j++) {
        float2 v = fa[j];
        v.x = fmaxf(v.x * inv17, 0.0f);
        v.y = fmaxf(v.y * inv17, 0.0f);
        fa[j] = v;
        ss += v.x * v.x + v.y * v.y;
    }
    // reduce across the 16 lanes of this node
    ss += __shfl_xor_sync(0xffffffffu, ss, 1);
    ss += __shfl_xor_sync(0xffffffffu, ss, 2);
    ss += __shfl_xor_sync(0xffffffffu, ss, 4);
    ss += __shfl_xor_sync(0xffffffffu, ss, 8);

    const float inv = 1.0f / fmaxf(sqrtf(ss), 1e-12f);
    if (valid) {
        if (HALF_OUT) {
            __half2 h[4];
            #pragma unroll
            for (int j = 0; j < 4; j++)
                h[j] = __float22half2_rn(make_float2(fa[j].x * inv, fa[j].y * inv));
            ((uint4*)((__half*)outv + (size_t)node * DIM))[o] =
                make_uint4(*(unsigned*)&h[0], *(unsigned*)&h[1],
                           *(unsigned*)&h[2], *(unsigned*)&h[3]);
        } else {
            float4* orow = (float4*)((float*)outv + (size_t)node * DIM);
            orow[2 * o]     = make_float4(fa[0].x * inv, fa[0].y * inv,
                                          fa[1].x * inv, fa[1].y * inv);
            orow[2 * o + 1] = make_float4(fa[2].x * inv, fa[2].y * inv,
                                          fa[3].x * inv, fa[3].y * inv);
        }
    }
}

// ---------------------------------------------------------------------------
extern "C" void kernel_launch(void* const* d_in, const int* in_sizes, int n_in,
                              void* d_out, int out_size)
{
    const float* feat = (const float*)d_in[0];   // [N, 64]
    const float* wf   = (const float*)d_in[1];   // [128, 64]
    const float* w1   = (const float*)d_in[2];   // [128, 128]
    const float* w2   = (const float*)d_in[3];   // [128, 128]
    const int*   n1   = (const int*)d_in[4];     // [N, 16]
    const int*   n2   = (const int*)d_in[5];     // [N, 16]
    float* out = (float*)d_out;                  // [N, 128]

    void *pz = nullptr, *px1 = nullptr, *pwc = nullptr;
    cudaGetSymbolAddress(&pz, g_z);
    cudaGetSymbolAddress(&px1, g_x1h);
    cudaGetSymbolAddress(&pwc, g_wc);
    __half* z   = (__half*)pz;
    __half* x1h = (__half*)px1;
    float*  wc  = (float*)pwc;

    const size_t SM64  = (size_t)DIM * (FIN / 2) * sizeof(uint2);   // 32 KB
    const size_t SM128 = (size_t)DIM * (DIM / 2) * sizeof(uint2);   // 64 KB
    cudaFuncSetAttribute((const void*)gemm_wsplit<FIN, true>,
                         cudaFuncAttributeMaxDynamicSharedMemorySize, (int)SM64);
    cudaFuncSetAttribute((const void*)gemm_wsplit<DIM, false>,
                         cudaFuncAttributeMaxDynamicSharedMemorySize, (int)SM128);

    const int gemm_grid = (NNODES + 127) / 128;     // 782
    const int gn_grid   = (NNODES + 15) / 16;       // 6250

    // wc = w1 @ wf  (folds layer-1 GEMM into the feature GEMM)
    wc_kernel<<<32, 256>>>(w1, wf, wc);
    // z1 = feat @ wc^T   (fp32 A converted in-kernel, fp16 out)
    gemm_wsplit<FIN, true><<<gemm_grid, 256, SM64>>>(feat, wc, z, NNODES);
    // x1 = normalize(relu(agg(z1)))  -> fp16
    gathernorm<true><<<gn_grid, 256>>>(z, n1, x1h);
    // z2 = x1 @ w2^T     (fp16 out)
    gemm_wsplit<DIM, false><<<gemm_grid, 256, SM128>>>(x1h, w2, z, NNODES);
    // out = normalize(relu(agg(z2))) -> fp32
    gathernorm<false><<<gn_grid, 256>>>(z, n2, out);
}

// round 11
// speedup vs baseline: 3.8733x; 1.0950x over previous
#include <cuda_runtime.h>
#include <cuda_fp16.h>

#define NNODES 100000
#define DIM 128
#define FIN 64
#define SAMP 16

// Scratch (module-load allocated; no runtime alloc)
__device__ __half g_z  [(size_t)NNODES * DIM];   // pre-aggregation embeddings
__device__ __half g_x1h[(size_t)NNODES * DIM];   // layer-1 output (fp16)
__device__ float  g_wc [DIM * FIN];              // folded w1 @ wf

// ---------------------------------------------------------------------------
// wc = w1 @ wf   [128,128]@[128,64] -> [128,64]
// ---------------------------------------------------------------------------
__global__ void wc_kernel(const float* __restrict__ w1,
                          const float* __restrict__ wf,
                          float* __restrict__ wc)
{
    int idx = blockIdx.x * 256 + threadIdx.x;      // 8192 outputs
    if (idx >= DIM * FIN) return;
    int i = idx >> 6, j = idx & 63;
    float s = 0.0f;
    #pragma unroll 8
    for (int t = 0; t < DIM; t++)
        s = fmaf(w1[i * DIM + t], wf[t * FIN + j], s);
    wc[i * FIN + j] = s;
}

// ---------------------------------------------------------------------------
// Dense GEMM: C[nrows,128](fp16) = A[nrows,K] @ W[128,K]^T(fp32->fp16)
// Single-term fp16 MMA (W-lo dropped; error budget covers it).
// Smem stores PAIRED b-fragment columns: Wp[n][ks*4+c] = {hi(k2+c), hi(k2+c+4)}
// -> one LDS.64 per MMA. 256 thr, warp = m16 x n128, 2 CTAs/SM.
// ---------------------------------------------------------------------------
#define MMA_F16(D, A0,A1,A2,A3, B0,B1)                                       \
    asm volatile("mma.sync.aligned.m16n8k16.row.col.f32.f16.f16.f32 "        \
                 "{%0,%1,%2,%3},{%4,%5,%6,%7},{%8,%9},{%0,%1,%2,%3};"        \
                 : "+f"(D[0]), "+f"(D[1]), "+f"(D[2]), "+f"(D[3])            \
                 : "r"(A0), "r"(A1), "r"(A2), "r"(A3), "r"(B0), "r"(B1))

template<int K, bool AF32>
__global__ __launch_bounds__(256, 2)
void gemm_whi(const void* __restrict__ Av,
              const float* __restrict__ W,
              __half* __restrict__ C, int nrows)
{
    constexpr int P  = K / 4;                     // paired-column slots per row
    constexpr int PM = P - 1;                     // swizzle mask
    extern __shared__ uint2 WP[];                 // [DIM][P] {hi(col), hi(col+4)}

    const int tid = threadIdx.x;

    // Stage W paired: p = ks*4 + c -> half2 cols (ks*8+c, ks*8+c+4)
    for (int idx = tid; idx < DIM * P; idx += 256) {
        int n = idx / P, p = idx % P;
        int ks = p >> 2, c = p & 3;
        const float* row = W + n * K + ks * 16 + 2 * c;
        __half2 h0 = __float22half2_rn(*(const float2*)&row[0]);
        __half2 h1 = __float22half2_rn(*(const float2*)&row[8]);
        int sp = p ^ (((n & 7) << 2) & PM);
        WP[n * P + sp] = make_uint2(*(unsigned*)&h0, *(unsigned*)&h1);
    }
    __syncthreads();

    const int warp = tid >> 5, lane = tid & 31;
    const int g = lane >> 2, c = lane & 3;

    long mrow = (long)blockIdx.x * 128 + warp * 16 + g;
    long r0 = mrow     < nrows ? mrow     : nrows - 1;
    long r1 = mrow + 8 < nrows ? mrow + 8 : nrows - 1;

    float d[16][4];
    #pragma unroll
    for (int nt = 0; nt < 16; nt++)
        #pragma unroll
        for (int q = 0; q < 4; q++) d[nt][q] = 0.0f;

    const int gswm = (g << 2) & PM;

    #pragma unroll 2
    for (int ks = 0; ks < K / 16; ks++) {
        const int k = ks * 16;
        unsigned a0, a1, a2, a3;
        if constexpr (AF32) {
            const float* A0f = (const float*)Av + r0 * K;
            const float* A1f = (const float*)Av + r1 * K;
            __half2 h;
            h = __float22half2_rn(*(const float2*)&A0f[k + 2 * c]);     a0 = *(unsigned*)&h;
            h = __float22half2_rn(*(const float2*)&A1f[k + 2 * c]);     a1 = *(unsigned*)&h;
            h = __float22half2_rn(*(const float2*)&A0f[k + 2 * c + 8]); a2 = *(unsigned*)&h;
            h = __float22half2_rn(*(const float2*)&A1f[k + 2 * c + 8]); a3 = *(unsigned*)&h;
        } else {
            const __half* A0h = (const __half*)Av + r0 * K;
            const __half* A1h = (const __half*)Av + r1 * K;
            a0 = *(const unsigned*)&A0h[k + 2 * c];
            a1 = *(const unsigned*)&A1h[k + 2 * c];
            a2 = *(const unsigned*)&A0h[k + 2 * c + 8];
            a3 = *(const unsigned*)&A1h[k + 2 * c + 8];
        }

        const int col = (ks * 4 + c) ^ gswm;

        #pragma unroll
        for (int nt = 0; nt < 16; nt++) {
            uint2 b = WP[(size_t)(nt * 8 + g) * P + col];
            MMA_F16(d[nt], a0, a1, a2, a3, b.x, b.y);
        }
    }

    long wr0 = (long)blockIdx.x * 128 + warp * 16 + g;
    long wr1 = wr0 + 8;
    #pragma unroll
    for (int nt = 0; nt < 16; nt++) {
        int col = nt * 8 + 2 * c;
        if (wr0 < nrows) {
            __half2 h = __float22half2_rn(make_float2(d[nt][0], d[nt][1]));
            *(__half2*)&C[wr0 * DIM + col] = h;
        }
        if (wr1 < nrows) {
            __half2 h = __float22half2_rn(make_float2(d[nt][2], d[nt][3]));
            *(__half2*)&C[wr1 * DIM + col] = h;
        }
    }
}

// ---------------------------------------------------------------------------
// gathernorm: out[n] = normalize(relu((z[n] + sum_s z[nb[n,s]]) / 17))
// 16 lanes/node, lane o owns one 16B chunk (17 x LDG.128 per thread).
// Neighbors in 4 groups of 4: 2-level fp16 tree then one fp32 accumulate.
// ---------------------------------------------------------------------------
template<bool HALF_OUT>
__global__ __launch_bounds__(256)
void gathernorm(const __half* __restrict__ z,
                const int*    __restrict__ nb,
                void*         __restrict__ outv)
{
    const int tid = threadIdx.x;
    const int m = tid >> 4;          // node in block (0..15)
    const int o = tid & 15;          // 16B chunk of the row
    int node = blockIdx.x * 16 + m;
    const bool valid = node < NNODES;
    if (!valid) node = NNODES - 1;

    // self chunk
    float2 fa[4];
    {
        uint4 u = ((const uint4*)(z + (size_t)node * DIM))[o];
        const __half2* h = (const __half2*)&u;
        #pragma unroll
        for (int j = 0; j < 4; j++) fa[j] = __half22float2(h[j]);
    }

    const int4* nrow = (const int4*)(nb + node * SAMP);

    #pragma unroll
    for (int sp = 0; sp < 4; sp++) {
        int4 id = nrow[sp];
        uint4 ua = ((const uint4*)(z + (size_t)id.x * DIM))[o];
        uint4 ub = ((const uint4*)(z + (size_t)id.y * DIM))[o];
        uint4 uc = ((const uint4*)(z + (size_t)id.z * DIM))[o];
        uint4 ud = ((const uint4*)(z + (size_t)id.w * DIM))[o];
        const __half2* ha = (const __half2*)&ua;
        const __half2* hb = (const __half2*)&ub;
        const __half2* hc = (const __half2*)&uc;
        const __half2* hd = (const __half2*)&ud;
        #pragma unroll
        for (int j = 0; j < 4; j++) {
            __half2 t = __hadd2(__hadd2(ha[j], hb[j]), __hadd2(hc[j], hd[j]));
            float2 f = __half22float2(t);
            fa[j].x += f.x;
            fa[j].y += f.y;
        }
    }

    const float inv17 = 1.0f / (float)(SAMP + 1);
    float ss = 0.0f;
    #pragma unroll
    for (int j = 0; j < 4; j++) {
        float2 v = fa[j];
        v.x = fmaxf(v.x * inv17, 0.0f);
        v.y = fmaxf(v.y * inv17, 0.0f);
        fa[j] = v;
        ss += v.x * v.x + v.y * v.y;
    }
    // reduce across the 16 lanes of this node
    ss += __shfl_xor_sync(0xffffffffu, ss, 1);
    ss += __shfl_xor_sync(0xffffffffu, ss, 2);
    ss += __shfl_xor_sync(0xffffffffu, ss, 4);
    ss += __shfl_xor_sync(0xffffffffu, ss, 8);

    const float inv = 1.0f / fmaxf(sqrtf(ss), 1e-12f);
    if (valid) {
        if (HALF_OUT) {
            __half2 h[4];
            #pragma unroll
            for (int j = 0; j < 4; j++)
                h[j] = __float22half2_rn(make_float2(fa[j].x * inv, fa[j].y * inv));
            ((uint4*)((__half*)outv + (size_t)node * DIM))[o] =
                make_uint4(*(unsigned*)&h[0], *(unsigned*)&h[1],
                           *(unsigned*)&h[2], *(unsigned*)&h[3]);
        } else {
            float4* orow = (float4*)((float*)outv + (size_t)node * DIM);
            orow[2 * o]     = make_float4(fa[0].x * inv, fa[0].y * inv,
                                          fa[1].x * inv, fa[1].y * inv);
            orow[2 * o + 1] = make_float4(fa[2].x * inv, fa[2].y * inv,
                                          fa[3].x * inv, fa[3].y * inv);
        }
    }
}

// ---------------------------------------------------------------------------
extern "C" void kernel_launch(void* const* d_in, const int* in_sizes, int n_in,
                              void* d_out, int out_size)
{
    const float* feat = (const float*)d_in[0];   // [N, 64]
    const float* wf   = (const float*)d_in[1];   // [128, 64]
    const float* w1   = (const float*)d_in[2];   // [128, 128]
    const float* w2   = (const float*)d_in[3];   // [128, 128]
    const int*   n1   = (const int*)d_in[4];     // [N, 16]
    const int*   n2   = (const int*)d_in[5];     // [N, 16]
    float* out = (float*)d_out;                  // [N, 128]

    void *pz = nullptr, *px1 = nullptr, *pwc = nullptr;
    cudaGetSymbolAddress(&pz, g_z);
    cudaGetSymbolAddress(&px1, g_x1h);
    cudaGetSymbolAddress(&pwc, g_wc);
    __half* z   = (__half*)pz;
    __half* x1h = (__half*)px1;
    float*  wc  = (float*)pwc;

    const size_t SM64  = (size_t)DIM * (FIN / 4) * sizeof(uint2);   // 16 KB
    const size_t SM128 = (size_t)DIM * (DIM / 4) * sizeof(uint2);   // 32 KB
    cudaFuncSetAttribute((const void*)gemm_whi<FIN, true>,
                         cudaFuncAttributeMaxDynamicSharedMemorySize, (int)SM64);
    cudaFuncSetAttribute((const void*)gemm_whi<DIM, false>,
                         cudaFuncAttributeMaxDynamicSharedMemorySize, (int)SM128);

    const int gemm_grid = (NNODES + 127) / 128;     // 782
    const int gn_grid   = (NNODES + 15) / 16;       // 6250

    // wc = w1 @ wf  (folds layer-1 GEMM into the feature GEMM)
    wc_kernel<<<32, 256>>>(w1, wf, wc);
    // z1 = feat @ wc^T   (fp32 A converted in-kernel, fp16 out)
    gemm_whi<FIN, true><<<gemm_grid, 256, SM64>>>(feat, wc, z, NNODES);
    // x1 = normalize(relu(agg(z1)))  -> fp16
    gathernorm<true><<<gn_grid, 256>>>(z, n1, x1h);
    // z2 = x1 @ w2^T     (fp16 out)
    gemm_whi<DIM, false><<<gemm_grid, 256, SM128>>>(x1h, w2, z, NNODES);
    // out = normalize(relu(agg(z2))) -> fp32
    gathernorm<false><<<gn_grid, 256>>>(z, n2, out);
}

// round 13
// speedup vs baseline: 4.0786x; 1.0530x over previous
#include <cuda_runtime.h>
#include <cuda_fp16.h>

#define NNODES 100000
#define DIM 128
#define FIN 64
#define SAMP 16

// Scratch (module-load allocated; no runtime alloc)
__device__ __half g_z  [(size_t)NNODES * DIM];   // pre-aggregation embeddings
__device__ __half g_x1h[(size_t)NNODES * DIM];   // layer-1 output (fp16)
__device__ float  g_wc [DIM * FIN];              // folded w1 @ wf

// ---------------------------------------------------------------------------
// wc = w1 @ wf   [128,128]@[128,64] -> [128,64]
// ---------------------------------------------------------------------------
__global__ void wc_kernel(const float* __restrict__ w1,
                          const float* __restrict__ wf,
                          float* __restrict__ wc)
{
    int idx = blockIdx.x * 256 + threadIdx.x;      // 8192 outputs
    if (idx >= DIM * FIN) return;
    int i = idx >> 6, j = idx & 63;
    float s = 0.0f;
    #pragma unroll 8
    for (int t = 0; t < DIM; t++)
        s = fmaf(w1[i * DIM + t], wf[t * FIN + j], s);
    wc[i * FIN + j] = s;
}

// ---------------------------------------------------------------------------
// Dense GEMM: C[nrows,128](fp16) = A[nrows,K] @ W[128,K]^T(fp32->fp16 hi)
// Tensor-core kernel, fully smem-resident:
//   A tile [128,K] staged swizzled -> fragments via ldmatrix.m8n8.x4
//   W staged as paired b-fragments -> one LDS.64 per MMA
//   epilogue via smem -> 512B-contiguous STG.128
// 256 thr, warp = m16 x n128, 2 CTAs/SM.
// ---------------------------------------------------------------------------
#define MMA_F16(D, A0,A1,A2,A3, B0,B1)                                       \
    asm volatile("mma.sync.aligned.m16n8k16.row.col.f32.f16.f16.f32 "        \
                 "{%0,%1,%2,%3},{%4,%5,%6,%7},{%8,%9},{%0,%1,%2,%3};"        \
                 : "+f"(D[0]), "+f"(D[1]), "+f"(D[2]), "+f"(D[3])            \
                 : "r"(A0), "r"(A1), "r"(A2), "r"(A3), "r"(B0), "r"(B1))

#define LDSM_X4(R0,R1,R2,R3, ADDR)                                           \
    asm volatile("ldmatrix.sync.aligned.m8n8.x4.shared.b16 {%0,%1,%2,%3}, [%4];" \
                 : "=r"(R0), "=r"(R1), "=r"(R2), "=r"(R3) : "r"(ADDR))

#define EPI_STRIDE 272          // bytes per epilogue smem row (conflict-free)
#define EPI_BYTES  (8 * 16 * EPI_STRIDE)   // 34816 B (>= A tile for K<=128)

template<int K, bool AF32>
__global__ __launch_bounds__(256, 2)
void gemm_tc(const void* __restrict__ Av,
             const float* __restrict__ W,
             __half* __restrict__ C, int nrows)
{
    constexpr int P   = K / 4;                    // paired-column slots per W row
    constexpr int PM  = P - 1;
    constexpr int CH  = K / 8;                    // uint4 chunks per A row
    constexpr int CHM = CH - 1;

    extern __shared__ char smraw[];
    uint2* WP  = (uint2*)smraw;                           // [DIM][P]
    char*  EPI = smraw + (size_t)DIM * P * sizeof(uint2); // epilogue / A-tile region
    uint4* AS  = (uint4*)EPI;                             // [128][CH] swizzled

    const int tid = threadIdx.x;
    const long rowbase = (long)blockIdx.x * 128;

    // ---- Stage W paired: p = ks*4+c -> half2 cols (ks*8+c, ks*8+c+4) ------
    for (int idx = tid; idx < DIM * P; idx += 256) {
        int n = idx / P, p = idx % P;
        int ks = p >> 2, c = p & 3;
        const float* row = W + n * K + ks * 16 + 2 * c;
        __half2 h0 = __float22half2_rn(*(const float2*)&row[0]);
        __half2 h1 = __float22half2_rn(*(const float2*)&row[8]);
        int sp = p ^ (((n & 7) << 2) & PM);
        WP[n * P + sp] = make_uint2(*(unsigned*)&h0, *(unsigned*)&h1);
    }

    // ---- Stage A tile [128, K] swizzled (coalesced loads) -----------------
    for (int idx = tid; idx < 128 * CH; idx += 256) {
        int r = idx / CH, ch = idx % CH;
        long gr = rowbase + r;
        if (gr >= nrows) gr = nrows - 1;
        uint4 v;
        if constexpr (AF32) {
            const float* src = (const float*)Av + gr * K + ch * 8;
            __half2 h0 = __float22half2_rn(*(const float2*)&src[0]);
            __half2 h1 = __float22half2_rn(*(const float2*)&src[2]);
            __half2 h2 = __float22half2_rn(*(const float2*)&src[4]);
            __half2 h3 = __float22half2_rn(*(const float2*)&src[6]);
            v = make_uint4(*(unsigned*)&h0, *(unsigned*)&h1,
                           *(unsigned*)&h2, *(unsigned*)&h3);
        } else {
            v = *(const uint4*)((const __half*)Av + gr * K + ch * 8);
        }
        AS[r * CH + (ch ^ ((r & 7) & CHM))] = v;
    }
    __syncthreads();

    const int warp = tid >> 5, lane = tid & 31;
    const int g = lane >> 2, c = lane & 3;
    const int slab = warp * 16;

    // ldmatrix source for this lane: matrix sel by lane/8, row within by lane%8
    const int lrow = slab + (lane & 7) + ((lane >> 3) & 1) * 8;
    const int lhi  = lane >> 4;                   // chunk offset 0/1 (k vs k+8)
    const int lsw  = (lrow & 7) & CHM;
    const unsigned as_u32 =
        (unsigned)__cvta_generic_to_shared(AS) + (unsigned)(lrow * CH) * 16u;

    float d[16][4];
    #pragma unroll
    for (int nt = 0; nt < 16; nt++)
        #pragma unroll
        for (int q = 0; q < 4; q++) d[nt][q] = 0.0f;

    const int gswm = (g << 2) & PM;

    #pragma unroll
    for (int ks = 0; ks < K / 16; ks++) {
        unsigned a0, a1, a2, a3;
        unsigned ad = as_u32 + (unsigned)(((ks * 2 + lhi) ^ lsw) * 16);
        LDSM_X4(a0, a1, a2, a3, ad);

        const int col = (ks * 4 + c) ^ gswm;
        #pragma unroll
        for (int nt = 0; nt < 16; nt++) {
            uint2 b = WP[(size_t)(nt * 8 + g) * P + col];
            MMA_F16(d[nt], a0, a1, a2, a3, b.x, b.y);
        }
    }

    __syncthreads();      // all LDSM reads done before epilogue reuses region

    // ---- Epilogue: STS -> LDS.128 -> contiguous STG.128 -------------------
    char* myepi = EPI + warp * (16 * EPI_STRIDE);
    #pragma unroll
    for (int nt = 0; nt < 16; nt++) {
        __half2 h0 = __float22half2_rn(make_float2(d[nt][0], d[nt][1]));
        __half2 h1 = __float22half2_rn(make_float2(d[nt][2], d[nt][3]));
        *(__half2*)(myepi + g * EPI_STRIDE + nt * 16 + 4 * c) = h0;
        *(__half2*)(myepi + (g + 8) * EPI_STRIDE + nt * 16 + 4 * c) = h1;
    }
    __syncwarp();
    {
        const int rr = lane >> 4;      // 0..1
        const int j  = lane & 15;      // 16B chunk within 256B row
        #pragma unroll
        for (int i = 0; i < 8; i++) {
            int r = i * 2 + rr;
            uint4 v = *(const uint4*)(myepi + r * EPI_STRIDE + j * 16);
            long gr = rowbase + slab + r;
            if (gr < nrows)
                *(uint4*)((char*)(C + gr * DIM) + j * 16) = v;
        }
    }
}

// ---------------------------------------------------------------------------
// gathernorm: out[n] = normalize(relu((z[n] + sum_s z[nb[n,s]]) / 17))
// 16 lanes/node, lane o owns one 16B chunk (17 x LDG.128 per thread).
// Neighbors in 4 groups of 4: 2-level fp16 tree then one fp32 accumulate.
// ---------------------------------------------------------------------------
template<bool HALF_OUT>
__global__ __launch_bounds__(256)
void gathernorm(const __half* __restrict__ z,
                const int*    __restrict__ nb,
                void*         __restrict__ outv)
{
    const int tid = threadIdx.x;
    const int m = tid >> 4;          // node in block (0..15)
    const int o = tid & 15;          // 16B chunk of the row
    int node = blockIdx.x * 16 + m;
    const bool valid = node < NNODES;
    if (!valid) node = NNODES - 1;

    float2 fa[4];
    {
        uint4 u = ((const uint4*)(z + (size_t)node * DIM))[o];
        const __half2* h = (const __half2*)&u;
        #pragma unroll
        for (int j = 0; j < 4; j++) fa[j] = __half22float2(h[j]);
    }

    const int4* nrow = (const int4*)(nb + node * SAMP);

    #pragma unroll
    for (int sp = 0; sp < 4; sp++) {
        int4 id = nrow[sp];
        uint4 ua = ((const uint4*)(z + (size_t)id.x * DIM))[o];
        uint4 ub = ((const uint4*)(z + (size_t)id.y * DIM))[o];
        uint4 uc = ((const uint4*)(z + (size_t)id.z * DIM))[o];
        uint4 ud = ((const uint4*)(z + (size_t)id.w * DIM))[o];
        const __half2* ha = (const __half2*)&ua;
        const __half2* hb = (const __half2*)&ub;
        const __half2* hc = (const __half2*)&uc;
        const __half2* hd = (const __half2*)&ud;
        #pragma unroll
        for (int j = 0; j < 4; j++) {
            __half2 t = __hadd2(__hadd2(ha[j], hb[j]), __hadd2(hc[j], hd[j]));
            float2 f = __half22float2(t);
            fa[j].x += f.x;
            fa[j].y += f.y;
        }
    }

    const float inv17 = 1.0f / (float)(SAMP + 1);
    float ss = 0.0f;
    #pragma unroll
    for (int j = 0; j < 4; j++) {
        float2 v = fa[j];
        v.x = fmaxf(v.x * inv17, 0.0f);
        v.y = fmaxf(v.y * inv17, 0.0f);
        fa[j] = v;
        ss += v.x * v.x + v.y * v.y;
    }
    ss += __shfl_xor_sync(0xffffffffu, ss, 1);
    ss += __shfl_xor_sync(0xffffffffu, ss, 2);
    ss += __shfl_xor_sync(0xffffffffu, ss, 4);
    ss += __shfl_xor_sync(0xffffffffu, ss, 8);

    const float inv = 1.0f / fmaxf(sqrtf(ss), 1e-12f);
    if (valid) {
        if (HALF_OUT) {
            __half2 h[4];
            #pragma unroll
            for (int j = 0; j < 4; j++)
                h[j] = __float22half2_rn(make_float2(fa[j].x * inv, fa[j].y * inv));
            ((uint4*)((__half*)outv + (size_t)node * DIM))[o] =
                make_uint4(*(unsigned*)&h[0], *(unsigned*)&h[1],
                           *(unsigned*)&h[2], *(unsigned*)&h[3]);
        } else {
            float4* orow = (float4*)((float*)outv + (size_t)node * DIM);
            orow[2 * o]     = make_float4(fa[0].x * inv, fa[0].y * inv,
                                          fa[1].x * inv, fa[1].y * inv);
            orow[2 * o + 1] = make_float4(fa[2].x * inv, fa[2].y * inv,
                                          fa[3].x * inv, fa[3].y * inv);
        }
    }
}

// ---------------------------------------------------------------------------
extern "C" void kernel_launch(void* const* d_in, const int* in_sizes, int n_in,
                              void* d_out, int out_size)
{
    const float* feat = (const float*)d_in[0];   // [N, 64]
    const float* wf   = (const float*)d_in[1];   // [128, 64]
    const float* w1   = (const float*)d_in[2];   // [128, 128]
    const float* w2   = (const float*)d_in[3];   // [128, 128]
    const int*   n1   = (const int*)d_in[4];     // [N, 16]
    const int*   n2   = (const int*)d_in[5];     // [N, 16]
    float* out = (float*)d_out;                  // [N, 128]

    void *pz = nullptr, *px1 = nullptr, *pwc = nullptr;
    cudaGetSymbolAddress(&pz, g_z);
    cudaGetSymbolAddress(&px1, g_x1h);
    cudaGetSymbolAddress(&pwc, g_wc);
    __half* z   = (__half*)pz;
    __half* x1h = (__half*)px1;
    float*  wc  = (float*)pwc;

    const size_t SM64  = (size_t)DIM * (FIN / 4) * sizeof(uint2) + EPI_BYTES; // ~50 KB
    const size_t SM128 = (size_t)DIM * (DIM / 4) * sizeof(uint2) + EPI_BYTES; // ~66 KB
    cudaFuncSetAttribute((const void*)gemm_tc<FIN, true>,
                         cudaFuncAttributeMaxDynamicSharedMemorySize, (int)SM64);
    cudaFuncSetAttribute((const void*)gemm_tc<DIM, false>,
                         cudaFuncAttributeMaxDynamicSharedMemorySize, (int)SM128);

    const int gemm_grid = (NNODES + 127) / 128;     // 782
    const int gn_grid   = (NNODES + 15) / 16;       // 6250

    // wc = w1 @ wf  (folds layer-1 GEMM into the feature GEMM)
    wc_kernel<<<32, 256>>>(w1, wf, wc);
    // z1 = feat @ wc^T   (fp32 A converted while staging, fp16 out)
    gemm_tc<FIN, true><<<gemm_grid, 256, SM64>>>(feat, wc, z, NNODES);
    // x1 = normalize(relu(agg(z1)))  -> fp16
    gathernorm<true><<<gn_grid, 256>>>(z, n1, x1h);
    // z2 = x1 @ w2^T     (fp16 out)
    gemm_tc<DIM, false><<<gemm_grid, 256, SM128>>>(x1h, w2, z, NNODES);
    // out = normalize(relu(agg(z2))) -> fp32
    gathernorm<false><<<gn_grid, 256>>>(z, n2, out);
}

// round 14
// speedup vs baseline: 4.3598x; 1.0689x over previous
#include <cuda_runtime.h>
#include <cuda_fp16.h>

#define NNODES 100000
#define DIM 128
#define FIN 64
#define SAMP 16

// Scratch (module-load allocated; no runtime alloc)
__device__ __half g_z  [(size_t)NNODES * DIM];   // pre-aggregation embeddings
__device__ __half g_x1h[(size_t)NNODES * DIM];   // layer-1 output (fp16)
__device__ float  g_wc [DIM * FIN];              // folded w1 @ wf

// ---------------------------------------------------------------------------
// wc = w1 @ wf   [128,128]@[128,64] -> [128,64]
// ---------------------------------------------------------------------------
__global__ void wc_kernel(const float* __restrict__ w1,
                          const float* __restrict__ wf,
                          float* __restrict__ wc)
{
    int idx = blockIdx.x * 256 + threadIdx.x;      // 8192 outputs
    if (idx >= DIM * FIN) return;
    int i = idx >> 6, j = idx & 63;
    float s = 0.0f;
    #pragma unroll 8
    for (int t = 0; t < DIM; t++)
        s = fmaf(w1[i * DIM + t], wf[t * FIN + j], s);
    wc[i * FIN + j] = s;
}

// ---------------------------------------------------------------------------
// Dense GEMM: C[nrows,128](fp16) = A[nrows,K] @ W[128,K]^T(fp32->fp16 hi)
// smem-resident tensor-core kernel; A tile staged via cp.async (fp16 path),
// fragments via ldmatrix.m8n8.x4; W as paired b-fragments (one LDS.64/MMA);
// epilogue via smem -> contiguous STG.128. 256 thr, 3 CTAs/SM.
// ---------------------------------------------------------------------------
#define MMA_F16(D, A0,A1,A2,A3, B0,B1)                                       \
    asm volatile("mma.sync.aligned.m16n8k16.row.col.f32.f16.f16.f32 "        \
                 "{%0,%1,%2,%3},{%4,%5,%6,%7},{%8,%9},{%0,%1,%2,%3};"        \
                 : "+f"(D[0]), "+f"(D[1]), "+f"(D[2]), "+f"(D[3])            \
                 : "r"(A0), "r"(A1), "r"(A2), "r"(A3), "r"(B0), "r"(B1))

#define LDSM_X4(R0,R1,R2,R3, ADDR)                                           \
    asm volatile("ldmatrix.sync.aligned.m8n8.x4.shared.b16 {%0,%1,%2,%3}, [%4];" \
                 : "=r"(R0), "=r"(R1), "=r"(R2), "=r"(R3) : "r"(ADDR))

#define CP_ASYNC16(DST_U32, SRC)                                             \
    asm volatile("cp.async.cg.shared.global [%0], [%1], 16;"                 \
                 :: "r"(DST_U32), "l"(SRC))
#define CP_ASYNC_FLUSH()                                                     \
    asm volatile("cp.async.commit_group;\n\tcp.async.wait_group 0;" ::: "memory")

#define EPI_STRIDE 272          // bytes per epilogue smem row (conflict-free)
#define EPI_BYTES  (8 * 16 * EPI_STRIDE)   // 34816 B (>= A tile for K<=128)

template<int K, bool AF32>
__global__ __launch_bounds__(256, 3)
void gemm_tc(const void* __restrict__ Av,
             const float* __restrict__ W,
             __half* __restrict__ C, int nrows)
{
    constexpr int P   = K / 4;                    // paired-column slots per W row
    constexpr int PM  = P - 1;
    constexpr int CH  = K / 8;                    // uint4 chunks per A row
    constexpr int CHM = CH - 1;

    extern __shared__ char smraw[];
    uint2* WP  = (uint2*)smraw;                           // [DIM][P]
    char*  EPI = smraw + (size_t)DIM * P * sizeof(uint2); // epilogue / A-tile region
    uint4* AS  = (uint4*)EPI;                             // [128][CH] swizzled

    const int tid = threadIdx.x;
    const int rowbase = blockIdx.x * 128;

    // ---- Stage A tile [128, K] swizzled ----------------------------------
    if constexpr (AF32) {
        for (int idx = tid; idx < 128 * CH; idx += 256) {
            int r = idx / CH, ch = idx % CH;
            int gr = rowbase + r;
            if (gr >= nrows) gr = nrows - 1;
            const float* src = (const float*)Av + (size_t)gr * K + ch * 8;
            __half2 h0 = __float22half2_rn(*(const float2*)&src[0]);
            __half2 h1 = __float22half2_rn(*(const float2*)&src[2]);
            __half2 h2 = __float22half2_rn(*(const float2*)&src[4]);
            __half2 h3 = __float22half2_rn(*(const float2*)&src[6]);
            AS[r * CH + (ch ^ ((r & 7) & CHM))] =
                make_uint4(*(unsigned*)&h0, *(unsigned*)&h1,
                           *(unsigned*)&h2, *(unsigned*)&h3);
        }
    } else {
        const unsigned as_b = (unsigned)__cvta_generic_to_shared(AS);
        for (int idx = tid; idx < 128 * CH; idx += 256) {
            int r = idx / CH, ch = idx % CH;
            int gr = rowbase + r;
            if (gr >= nrows) gr = nrows - 1;
            const __half* src = (const __half*)Av + (size_t)gr * K + ch * 8;
            unsigned dst = as_b + (unsigned)(r * CH + (ch ^ ((r & 7) & CHM))) * 16u;
            CP_ASYNC16(dst, src);
        }
    }

    // ---- Stage W paired: p = ks*4+c -> half2 cols (ks*8+c, ks*8+c+4) ------
    for (int idx = tid; idx < DIM * P; idx += 256) {
        int n = idx / P, p = idx % P;
        int ks = p >> 2, c = p & 3;
        const float* row = W + n * K + ks * 16 + 2 * c;
        __half2 h0 = __float22half2_rn(*(const float2*)&row[0]);
        __half2 h1 = __float22half2_rn(*(const float2*)&row[8]);
        int sp = p ^ (((n & 7) << 2) & PM);
        WP[n * P + sp] = make_uint2(*(unsigned*)&h0, *(unsigned*)&h1);
    }

    if constexpr (!AF32) CP_ASYNC_FLUSH();
    __syncthreads();

    const int warp = tid >> 5, lane = tid & 31;
    const int g = lane >> 2, c = lane & 3;
    const int slab = warp * 16;

    // ldmatrix source for this lane
    const int lrow = slab + (lane & 7) + ((lane >> 3) & 1) * 8;
    const int lhi  = lane >> 4;
    const int lsw  = (lrow & 7) & CHM;
    const unsigned as_u32 =
        (unsigned)__cvta_generic_to_shared(AS) + (unsigned)(lrow * CH) * 16u;

    float d[16][4];
    #pragma unroll
    for (int nt = 0; nt < 16; nt++)
        #pragma unroll
        for (int q = 0; q < 4; q++) d[nt][q] = 0.0f;

    const int gswm = (g << 2) & PM;

    #pragma unroll
    for (int ks = 0; ks < K / 16; ks++) {
        unsigned a0, a1, a2, a3;
        unsigned ad = as_u32 + (unsigned)(((ks * 2 + lhi) ^ lsw) * 16);
        LDSM_X4(a0, a1, a2, a3, ad);

        const int col = (ks * 4 + c) ^ gswm;
        #pragma unroll
        for (int nt = 0; nt < 16; nt++) {
            uint2 b = WP[(nt * 8 + g) * P + col];
            MMA_F16(d[nt], a0, a1, a2, a3, b.x, b.y);
        }
    }

    __syncthreads();      // all LDSM reads done before epilogue reuses region

    // ---- Epilogue: STS -> LDS.128 -> contiguous STG.128 -------------------
    char* myepi = EPI + warp * (16 * EPI_STRIDE);
    #pragma unroll
    for (int nt = 0; nt < 16; nt++) {
        __half2 h0 = __float22half2_rn(make_float2(d[nt][0], d[nt][1]));
        __half2 h1 = __float22half2_rn(make_float2(d[nt][2], d[nt][3]));
        *(__half2*)(myepi + g * EPI_STRIDE + nt * 16 + 4 * c) = h0;
        *(__half2*)(myepi + (g + 8) * EPI_STRIDE + nt * 16 + 4 * c) = h1;
    }
    __syncwarp();
    {
        const int rr = lane >> 4;      // 0..1
        const int j  = lane & 15;      // 16B chunk within 256B row
        #pragma unroll
        for (int i = 0; i < 8; i++) {
            int r = i * 2 + rr;
            uint4 v = *(const uint4*)(myepi + r * EPI_STRIDE + j * 16);
            int gr = rowbase + slab + r;
            if (gr < nrows)
                *(uint4*)((char*)(C + (size_t)gr * DIM) + j * 16) = v;
        }
    }
}

// ---------------------------------------------------------------------------
// gathernorm: out[n] = normalize(relu((z[n] + sum_s z[nb[n,s]]) / 17))
// 16 lanes/node, lane o owns one 16B chunk (17 x LDG.128 per thread).
// Neighbors in 4 groups of 4: 2-level fp16 tree then one fp32 accumulate.
// ---------------------------------------------------------------------------
template<bool HALF_OUT>
__global__ __launch_bounds__(256)
void gathernorm(const __half* __restrict__ z,
                const int*    __restrict__ nb,
                void*         __restrict__ outv)
{
    const int tid = threadIdx.x;
    const int m = tid >> 4;          // node in block (0..15)
    const int o = tid & 15;          // 16B chunk of the row
    int node = blockIdx.x * 16 + m;
    const bool valid = node < NNODES;
    if (!valid) node = NNODES - 1;

    float2 fa[4];
    {
        uint4 u = ((const uint4*)(z + (size_t)node * DIM))[o];
        const __half2* h = (const __half2*)&u;
        #pragma unroll
        for (int j = 0; j < 4; j++) fa[j] = __half22float2(h[j]);
    }

    const int4* nrow = (const int4*)(nb + node * SAMP);

    #pragma unroll
    for (int sp = 0; sp < 4; sp++) {
        int4 id = nrow[sp];
        uint4 ua = ((const uint4*)(z + (size_t)id.x * DIM))[o];
        uint4 ub = ((const uint4*)(z + (size_t)id.y * DIM))[o];
        uint4 uc = ((const uint4*)(z + (size_t)id.z * DIM))[o];
        uint4 ud = ((const uint4*)(z + (size_t)id.w * DIM))[o];
        const __half2* ha = (const __half2*)&ua;
        const __half2* hb = (const __half2*)&ub;
        const __half2* hc = (const __half2*)&uc;
        const __half2* hd = (const __half2*)&ud;
        #pragma unroll
        for (int j = 0; j < 4; j++) {
            __half2 t = __hadd2(__hadd2(ha[j], hb[j]), __hadd2(hc[j], hd[j]));
            float2 f = __half22float2(t);
            fa[j].x += f.x;
            fa[j].y += f.y;
        }
    }

    const float inv17 = 1.0f / (float)(SAMP + 1);
    float ss = 0.0f;
    #pragma unroll
    for (int j = 0; j < 4; j++) {
        float2 v = fa[j];
        v.x = fmaxf(v.x * inv17, 0.0f);
        v.y = fmaxf(v.y * inv17, 0.0f);
        fa[j] = v;
        ss += v.x * v.x + v.y * v.y;
    }
    ss += __shfl_xor_sync(0xffffffffu, ss, 1);
    ss += __shfl_xor_sync(0xffffffffu, ss, 2);
    ss += __shfl_xor_sync(0xffffffffu, ss, 4);
    ss += __shfl_xor_sync(0xffffffffu, ss, 8);

    const float inv = 1.0f / fmaxf(sqrtf(ss), 1e-12f);
    if (valid) {
        if (HALF_OUT) {
            __half2 h[4];
            #pragma unroll
            for (int j = 0; j < 4; j++)
                h[j] = __float22half2_rn(make_float2(fa[j].x * inv, fa[j].y * inv));
            ((uint4*)((__half*)outv + (size_t)node * DIM))[o] =
                make_uint4(*(unsigned*)&h[0], *(unsigned*)&h[1],
                           *(unsigned*)&h[2], *(unsigned*)&h[3]);
        } else {
            float4* orow = (float4*)((float*)outv + (size_t)node * DIM);
            orow[2 * o]     = make_float4(fa[0].x * inv, fa[0].y * inv,
                                          fa[1].x * inv, fa[1].y * inv);
            orow[2 * o + 1] = make_float4(fa[2].x * inv, fa[2].y * inv,
                                          fa[3].x * inv, fa[3].y * inv);
        }
    }
}

// ---------------------------------------------------------------------------
extern "C" void kernel_launch(void* const* d_in, const int* in_sizes, int n_in,
                              void* d_out, int out_size)
{
    const float* feat = (const float*)d_in[0];   // [N, 64]
    const float* wf   = (const float*)d_in[1];   // [128, 64]
    const float* w1   = (const float*)d_in[2];   // [128, 128]
    const float* w2   = (const float*)d_in[3];   // [128, 128]
    const int*   n1   = (const int*)d_in[4];     // [N, 16]
    const int*   n2   = (const int*)d_in[5];     // [N, 16]
    float* out = (float*)d_out;                  // [N, 128]

    void *pz = nullptr, *px1 = nullptr, *pwc = nullptr;
    cudaGetSymbolAddress(&pz, g_z);
    cudaGetSymbolAddress(&px1, g_x1h);
    cudaGetSymbolAddress(&pwc, g_wc);
    __half* z   = (__half*)pz;
    __half* x1h = (__half*)px1;
    float*  wc  = (float*)pwc;

    const size_t SM64  = (size_t)DIM * (FIN / 4) * sizeof(uint2) + EPI_BYTES; // ~50 KB
    const size_t SM128 = (size_t)DIM * (DIM / 4) * sizeof(uint2) + EPI_BYTES; // ~66 KB
    cudaFuncSetAttribute((const void*)gemm_tc<FIN, true>,
                         cudaFuncAttributeMaxDynamicSharedMemorySize, (int)SM64);
    cudaFuncSetAttribute((const void*)gemm_tc<DIM, false>,
                         cudaFuncAttributeMaxDynamicSharedMemorySize, (int)SM128);

    const int gemm_grid = (NNODES + 127) / 128;     // 782
    const int gn_grid   = (NNODES + 15) / 16;       // 6250

    // wc = w1 @ wf  (folds layer-1 GEMM into the feature GEMM)
    wc_kernel<<<32, 256>>>(w1, wf, wc);
    // z1 = feat @ wc^T   (fp32 A converted while staging, fp16 out)
    gemm_tc<FIN, true><<<gemm_grid, 256, SM64>>>(feat, wc, z, NNODES);
    // x1 = normalize(relu(agg(z1)))  -> fp16
    gathernorm<true><<<gn_grid, 256>>>(z, n1, x1h);
    // z2 = x1 @ w2^T     (fp16 out)
    gemm_tc<DIM, false><<<gemm_grid, 256, SM128>>>(x1h, w2, z, NNODES);
    // out = normalize(relu(agg(z2))) -> fp32
    gathernorm<false><<<gn_grid, 256>>>(z, n2, out);
}